// round 9
// baseline (speedup 1.0000x reference)
#include <cuda_runtime.h>
#include <math.h>
#include <stdint.h>

// Problem constants
#define Lc  4
#define Bc  8
#define Sc  1024
#define Dc  256
#define Hc  8
#define DHc 32
#define Ic  1024
#define Mc  4
#define TOK (Bc*Sc)          // 8192 tokens

// ---------------------------------------------------------------------------
// Scratch (no allocations allowed -> __device__ globals)
// ---------------------------------------------------------------------------
__device__ float g_h  [TOK*Dc];
__device__ float g_q  [TOK*Dc];
__device__ float g_k  [TOK*Dc];
__device__ float g_v  [TOK*Dc];
__device__ float g_ctx[TOK*Dc];
__device__ float g_tmp[TOK*Dc];
__device__ float g_ao [TOK*Dc];
__device__ float g_ff [TOK*Ic];

// ---------------------------------------------------------------------------
// Embedding + positional encoding: h[t,d] = emb[x[t],d] + pe[t%S, d]
// ---------------------------------------------------------------------------
__global__ void embed_kernel(const int* __restrict__ x,
                             const float* __restrict__ emb,
                             const float* __restrict__ pe)
{
    int gid = blockIdx.x * 256 + threadIdx.x;      // [0, TOK*Dc)
    int t = gid >> 8;
    int d = gid & 255;
    int tok = x[t];
    g_h[gid] = emb[tok * Dc + d] + pe[(t & (Sc - 1)) * Dc + d];
}

// ---------------------------------------------------------------------------
// Tiled SGEMM:  C[M,N] = A[M,K] @ W[N,K]^T + bias[N]  (torch Linear layout)
//   ep = 0: C = acc + bias
//   ep = 1: C = gelu_exact(acc + bias)
//   ep = 2: C = acc + bias + resid
// Tile: BM=128, BN=64, BK=16; 256 threads; 8x4 per thread.
// All dims divide evenly (M=8192, N in {256,1024}, K in {256,1024}).
// ---------------------------------------------------------------------------
#define GBM 128
#define GBN 64
#define GBK 16

__device__ __forceinline__ float gelu_exact(float v)
{
    return 0.5f * v * (1.0f + erff(v * 0.70710678118654752f));
}

__global__ __launch_bounds__(256)
void gemm_kernel(const float* __restrict__ A,
                 const float* __restrict__ W,
                 const float* __restrict__ bias,
                 const float* __restrict__ resid,
                 float* __restrict__ C,
                 int Ndim, int Kdim, int ep)
{
    __shared__ float As[GBK][GBM + 4];
    __shared__ float Bs[GBK][GBN + 4];

    const int tid  = threadIdx.x;
    const int row0 = blockIdx.y * GBM;
    const int col0 = blockIdx.x * GBN;
    const int tx   = tid & 15;   // N dir: 16 * 4 = 64
    const int ty   = tid >> 4;   // M dir: 16 * 8 = 128

    float acc[8][4];
#pragma unroll
    for (int i = 0; i < 8; i++)
#pragma unroll
        for (int j = 0; j < 4; j++) acc[i][j] = 0.f;

    for (int k0 = 0; k0 < Kdim; k0 += GBK) {
        // Load A tile (128x16 = 512 float4, 2 per thread), transposed into As[k][m]
#pragma unroll
        for (int i = 0; i < 2; i++) {
            int f  = tid + i * 256;
            int r  = f >> 2;
            int c4 = f & 3;
            float4 v = *(const float4*)(A + (size_t)(row0 + r) * Kdim + k0 + c4 * 4);
            As[c4 * 4 + 0][r] = v.x;
            As[c4 * 4 + 1][r] = v.y;
            As[c4 * 4 + 2][r] = v.z;
            As[c4 * 4 + 3][r] = v.w;
        }
        // Load B tile (64x16 = 256 float4, 1 per thread), transposed into Bs[k][n]
        {
            int r  = tid >> 2;
            int c4 = tid & 3;
            float4 v = *(const float4*)(W + (size_t)(col0 + r) * Kdim + k0 + c4 * 4);
            Bs[c4 * 4 + 0][r] = v.x;
            Bs[c4 * 4 + 1][r] = v.y;
            Bs[c4 * 4 + 2][r] = v.z;
            Bs[c4 * 4 + 3][r] = v.w;
        }
        __syncthreads();

#pragma unroll
        for (int k = 0; k < GBK; k++) {
            float a[8], bf[4];
            *(float4*)&a[0] = *(const float4*)&As[k][ty * 8];
            *(float4*)&a[4] = *(const float4*)&As[k][ty * 8 + 4];
            *(float4*)&bf[0] = *(const float4*)&Bs[k][tx * 4];
#pragma unroll
            for (int i = 0; i < 8; i++)
#pragma unroll
                for (int j = 0; j < 4; j++) acc[i][j] += a[i] * bf[j];
        }
        __syncthreads();
    }

    // Epilogue
    float4 bv = *(const float4*)(bias + col0 + tx * 4);
#pragma unroll
    for (int i = 0; i < 8; i++) {
        int r = row0 + ty * 8 + i;
        int c = col0 + tx * 4;
        float4 v;
        v.x = acc[i][0] + bv.x;
        v.y = acc[i][1] + bv.y;
        v.z = acc[i][2] + bv.z;
        v.w = acc[i][3] + bv.w;
        if (ep == 1) {
            v.x = gelu_exact(v.x); v.y = gelu_exact(v.y);
            v.z = gelu_exact(v.z); v.w = gelu_exact(v.w);
        } else if (ep == 2) {
            float4 rv = *(const float4*)(resid + (size_t)r * Ndim + c);
            v.x += rv.x; v.y += rv.y; v.z += rv.z; v.w += rv.w;
        }
        *(float4*)(C + (size_t)r * Ndim + c) = v;
    }
}

// ---------------------------------------------------------------------------
// Flash-style causal attention. grid = (S/128, B*H), block = 128.
// Thread = one query row; keys staged in 16-row smem tiles; online softmax.
// ---------------------------------------------------------------------------
__global__ __launch_bounds__(128)
void attn_kernel(const float* __restrict__ Q,
                 const float* __restrict__ Kp,
                 const float* __restrict__ Vp,
                 float* __restrict__ CTX)
{
    __shared__ float Ks[16][32];
    __shared__ float Vs[16][32];

    const int qt  = blockIdx.x;
    const int bh  = blockIdx.y;
    const int b   = bh >> 3;
    const int hh  = bh & 7;
    const int tid = threadIdx.x;
    const int qi  = qt * 128 + tid;

    const size_t qbase = ((size_t)(b * Sc + qi)) * Dc + hh * DHc;

    float qreg[32];
#pragma unroll
    for (int i = 0; i < 8; i++) {
        float4 t4 = *(const float4*)(Q + qbase + i * 4);
        qreg[i * 4 + 0] = t4.x; qreg[i * 4 + 1] = t4.y;
        qreg[i * 4 + 2] = t4.z; qreg[i * 4 + 3] = t4.w;
    }
    float acc[32];
#pragma unroll
    for (int d = 0; d < 32; d++) acc[d] = 0.f;

    float mx = -1e30f, l = 0.f;
    const float scale = 0.17677669529663689f;   // 1/sqrt(32)

    const int lr = tid >> 3;          // 0..15 (key row in tile)
    const int lc = (tid & 7) * 4;     // 0..28 (dh col, float4)
    const int kend = (qt + 1) * 128;

    for (int kt = 0; kt < kend; kt += 16) {
        const size_t kb = ((size_t)(b * Sc + kt + lr)) * Dc + hh * DHc + lc;
        __syncthreads();  // protect previous tile reads
        *(float4*)&Ks[lr][lc] = *(const float4*)(Kp + kb);
        *(float4*)&Vs[lr][lc] = *(const float4*)(Vp + kb);
        __syncthreads();

        float sv[16];
        float tmax = -1e30f;
#pragma unroll
        for (int kk = 0; kk < 16; kk++) {
            float dot = 0.f;
#pragma unroll
            for (int d4 = 0; d4 < 8; d4++) {
                float4 kv = *(const float4*)&Ks[kk][d4 * 4];
                dot += qreg[d4 * 4 + 0] * kv.x + qreg[d4 * 4 + 1] * kv.y
                     + qreg[d4 * 4 + 2] * kv.z + qreg[d4 * 4 + 3] * kv.w;
            }
            bool valid = (kt + kk) <= qi;
            float s = valid ? dot * scale : -1e30f;
            sv[kk] = s;
            tmax = fmaxf(tmax, s);
        }
        float mnew = fmaxf(mx, tmax);
        float corr = __expf(mx - mnew);   // exp(-1e30 - x) underflows to 0 cleanly
        mx = mnew;
        l *= corr;
#pragma unroll
        for (int d = 0; d < 32; d++) acc[d] *= corr;

#pragma unroll
        for (int kk = 0; kk < 16; kk++) {
            float p = (sv[kk] > -1e29f) ? __expf(sv[kk] - mnew) : 0.f;
            l += p;
#pragma unroll
            for (int d4 = 0; d4 < 8; d4++) {
                float4 vv = *(const float4*)&Vs[kk][d4 * 4];
                acc[d4 * 4 + 0] += p * vv.x;
                acc[d4 * 4 + 1] += p * vv.y;
                acc[d4 * 4 + 2] += p * vv.z;
                acc[d4 * 4 + 3] += p * vv.w;
            }
        }
    }

    const float inv = 1.f / l;
#pragma unroll
    for (int i = 0; i < 8; i++) {
        float4 o4 = make_float4(acc[i * 4 + 0] * inv, acc[i * 4 + 1] * inv,
                                acc[i * 4 + 2] * inv, acc[i * 4 + 3] * inv);
        *(float4*)(CTX + qbase + i * 4) = o4;
    }
}

// ---------------------------------------------------------------------------
// LayerNorm over last dim (256). One block (256 threads) per row. Two-pass.
// ---------------------------------------------------------------------------
__global__ __launch_bounds__(256)
void ln_kernel(const float* __restrict__ X,
               const float* __restrict__ gw,
               const float* __restrict__ bw,
               float* __restrict__ Y)
{
    const int row = blockIdx.x;
    const int d   = threadIdx.x;
    __shared__ float red[8];
    __shared__ float bc;

    float v = X[(size_t)row * Dc + d];

    // pass 1: mean
    float s = v;
#pragma unroll
    for (int o = 16; o > 0; o >>= 1) s += __shfl_down_sync(0xffffffffu, s, o);
    if ((d & 31) == 0) red[d >> 5] = s;
    __syncthreads();
    if (d == 0) {
        float t = 0.f;
#pragma unroll
        for (int i = 0; i < 8; i++) t += red[i];
        bc = t * (1.0f / Dc);
    }
    __syncthreads();
    const float m  = bc;
    const float dv = v - m;

    // pass 2: variance of (x - m)
    float s2 = dv * dv;
#pragma unroll
    for (int o = 16; o > 0; o >>= 1) s2 += __shfl_down_sync(0xffffffffu, s2, o);
    __syncthreads();                    // everyone has read bc; safe to reuse
    if ((d & 31) == 0) red[d >> 5] = s2;
    __syncthreads();
    if (d == 0) {
        float t = 0.f;
#pragma unroll
        for (int i = 0; i < 8; i++) t += red[i];
        bc = t * (1.0f / Dc);
    }
    __syncthreads();
    const float var = bc;

    Y[(size_t)row * Dc + d] = gw[d] * dv * rsqrtf(var + 1e-12f) + bw[d];
}

// ---------------------------------------------------------------------------
// Output projection: logits[t,m] = h[t,:] . out_w[m,:] + out_b[m]   (M=4)
// One warp per token; 8 warps per block.
// ---------------------------------------------------------------------------
__global__ __launch_bounds__(256)
void outproj_kernel(const float* __restrict__ ow,
                    const float* __restrict__ ob,
                    float* __restrict__ out)
{
    const int w    = threadIdx.x >> 5;
    const int lane = threadIdx.x & 31;
    const int t    = blockIdx.x * 8 + w;
    const float* hr = g_h + (size_t)t * Dc;

    float hv[8];
#pragma unroll
    for (int i = 0; i < 8; i++) hv[i] = hr[lane + 32 * i];

#pragma unroll
    for (int m = 0; m < Mc; m++) {
        const float* wr = ow + m * Dc;
        float p = 0.f;
#pragma unroll
        for (int i = 0; i < 8; i++) p += hv[i] * wr[lane + 32 * i];
#pragma unroll
        for (int o = 16; o > 0; o >>= 1) p += __shfl_down_sync(0xffffffffu, p, o);
        if (lane == 0) out[t * Mc + m] = p + ob[m];
    }
}

// ---------------------------------------------------------------------------
// Host orchestration (graph-capturable: kernel launches only)
// ---------------------------------------------------------------------------
extern "C" void kernel_launch(void* const* d_in, const int* in_sizes, int n_in,
                              void* d_out, int out_size)
{
    const int*   x     = (const int*)  d_in[0];
    const float* emb   = (const float*)d_in[1];
    const float* pe    = (const float*)d_in[2];
    const float* q_w   = (const float*)d_in[3];
    const float* q_b   = (const float*)d_in[4];
    const float* k_w   = (const float*)d_in[5];
    const float* k_b   = (const float*)d_in[6];
    const float* v_w   = (const float*)d_in[7];
    const float* v_b   = (const float*)d_in[8];
    const float* o_w   = (const float*)d_in[9];
    const float* o_b   = (const float*)d_in[10];
    const float* ln1_g = (const float*)d_in[11];
    const float* ln1_b = (const float*)d_in[12];
    const float* f1_w  = (const float*)d_in[13];
    const float* f1_b  = (const float*)d_in[14];
    const float* f2_w  = (const float*)d_in[15];
    const float* f2_b  = (const float*)d_in[16];
    const float* ln2_g = (const float*)d_in[17];
    const float* ln2_b = (const float*)d_in[18];
    const float* out_w = (const float*)d_in[19];
    const float* out_b = (const float*)d_in[20];
    float* out = (float*)d_out;

    float *h, *q, *k, *v, *ctx, *tmp, *ao, *ff;
    cudaGetSymbolAddress((void**)&h,   g_h);
    cudaGetSymbolAddress((void**)&q,   g_q);
    cudaGetSymbolAddress((void**)&k,   g_k);
    cudaGetSymbolAddress((void**)&v,   g_v);
    cudaGetSymbolAddress((void**)&ctx, g_ctx);
    cudaGetSymbolAddress((void**)&tmp, g_tmp);
    cudaGetSymbolAddress((void**)&ao,  g_ao);
    cudaGetSymbolAddress((void**)&ff,  g_ff);

    embed_kernel<<<TOK * Dc / 256, 256>>>(x, emb, pe);

    const dim3 gD(Dc / GBN, TOK / GBM);   // N=256 GEMMs:  (4, 64)
    const dim3 gI(Ic / GBN, TOK / GBM);   // N=1024 GEMM:  (16, 64)
    const dim3 gAttn(Sc / 128, Bc * Hc);  // (8, 64)

    for (int l = 0; l < Lc; l++) {
        const size_t wo  = (size_t)l * Dc * Dc;
        const size_t bo  = (size_t)l * Dc;
        const size_t f1o = (size_t)l * Ic * Dc;

        gemm_kernel<<<gD, 256>>>(h, q_w + wo, q_b + bo, nullptr, q, Dc, Dc, 0);
        gemm_kernel<<<gD, 256>>>(h, k_w + wo, k_b + bo, nullptr, k, Dc, Dc, 0);
        gemm_kernel<<<gD, 256>>>(h, v_w + wo, v_b + bo, nullptr, v, Dc, Dc, 0);

        attn_kernel<<<gAttn, 128>>>(q, k, v, ctx);

        // tmp = ctx @ o_w^T + o_b + h ; ao = LN1(tmp)
        gemm_kernel<<<gD, 256>>>(ctx, o_w + wo, o_b + bo, h, tmp, Dc, Dc, 2);
        ln_kernel<<<TOK, 256>>>(tmp, ln1_g + bo, ln1_b + bo, ao);

        // ff = gelu(ao @ f1^T + f1_b)
        gemm_kernel<<<gI, 256>>>(ao, f1_w + f1o, f1_b + (size_t)l * Ic, nullptr, ff, Ic, Dc, 1);
        // tmp = ff @ f2^T + f2_b + ao ; h = LN2(tmp)
        gemm_kernel<<<gD, 256>>>(ff, f2_w + f1o, f2_b + bo, ao, tmp, Dc, Ic, 2);
        ln_kernel<<<TOK, 256>>>(tmp, ln2_g + bo, ln2_b + bo, h);
    }

    outproj_kernel<<<TOK / 8, 256>>>(out_w, out_b, out);
}

// round 10
// speedup vs baseline: 1.0017x; 1.0017x over previous
#include <cuda_runtime.h>
#include <math.h>
#include <stdint.h>

// Problem constants
#define Lc  4
#define Bc  8
#define Sc  1024
#define Dc  256
#define Hc  8
#define DHc 32
#define Ic  1024
#define Mc  4
#define TOK (Bc*Sc)          // 8192 tokens

// ---------------------------------------------------------------------------
// Scratch (no allocations allowed -> __device__ globals)
// ---------------------------------------------------------------------------
__device__ float g_h  [TOK*Dc];
__device__ float g_q  [TOK*Dc];
__device__ float g_k  [TOK*Dc];
__device__ float g_v  [TOK*Dc];
__device__ float g_ctx[TOK*Dc];
__device__ float g_tmp[TOK*Dc];
__device__ float g_ao [TOK*Dc];
__device__ float g_ff [TOK*Ic];

// ---------------------------------------------------------------------------
// Embedding + positional encoding: h[t,d] = emb[x[t],d] + pe[t%S, d]
// ---------------------------------------------------------------------------
__global__ void embed_kernel(const int* __restrict__ x,
                             const float* __restrict__ emb,
                             const float* __restrict__ pe)
{
    int gid = blockIdx.x * 256 + threadIdx.x;      // [0, TOK*Dc)
    int t = gid >> 8;
    int d = gid & 255;
    int tok = x[t];
    g_h[gid] = emb[tok * Dc + d] + pe[(t & (Sc - 1)) * Dc + d];
}

// ---------------------------------------------------------------------------
// Tiled SGEMM:  C[M,N] = A[M,K] @ W[N,K]^T + bias[N]  (torch Linear layout)
//   ep = 0: C = acc + bias
//   ep = 1: C = gelu_exact(acc + bias)
//   ep = 2: C = acc + bias + resid
// Tile: BM=128, BN=64, BK=16; 256 threads; 8x4 per thread.
// All dims divide evenly (M=8192, N in {256,1024}, K in {256,1024}).
// ---------------------------------------------------------------------------
#define GBM 128
#define GBN 64
#define GBK 16

__device__ __forceinline__ float gelu_exact(float v)
{
    return 0.5f * v * (1.0f + erff(v * 0.70710678118654752f));
}

__global__ __launch_bounds__(256)
void gemm_kernel(const float* __restrict__ A,
                 const float* __restrict__ W,
                 const float* __restrict__ bias,
                 const float* __restrict__ resid,
                 float* __restrict__ C,
                 int Ndim, int Kdim, int ep)
{
    __shared__ float As[GBK][GBM + 4];
    __shared__ float Bs[GBK][GBN + 4];

    const int tid  = threadIdx.x;
    const int row0 = blockIdx.y * GBM;
    const int col0 = blockIdx.x * GBN;
    const int tx   = tid & 15;   // N dir: 16 * 4 = 64
    const int ty   = tid >> 4;   // M dir: 16 * 8 = 128

    float acc[8][4];
#pragma unroll
    for (int i = 0; i < 8; i++)
#pragma unroll
        for (int j = 0; j < 4; j++) acc[i][j] = 0.f;

    for (int k0 = 0; k0 < Kdim; k0 += GBK) {
        // Load A tile (128x16 = 512 float4, 2 per thread), transposed into As[k][m]
#pragma unroll
        for (int i = 0; i < 2; i++) {
            int f  = tid + i * 256;
            int r  = f >> 2;
            int c4 = f & 3;
            float4 v = *(const float4*)(A + (size_t)(row0 + r) * Kdim + k0 + c4 * 4);
            As[c4 * 4 + 0][r] = v.x;
            As[c4 * 4 + 1][r] = v.y;
            As[c4 * 4 + 2][r] = v.z;
            As[c4 * 4 + 3][r] = v.w;
        }
        // Load B tile (64x16 = 256 float4, 1 per thread), transposed into Bs[k][n]
        {
            int r  = tid >> 2;
            int c4 = tid & 3;
            float4 v = *(const float4*)(W + (size_t)(col0 + r) * Kdim + k0 + c4 * 4);
            Bs[c4 * 4 + 0][r] = v.x;
            Bs[c4 * 4 + 1][r] = v.y;
            Bs[c4 * 4 + 2][r] = v.z;
            Bs[c4 * 4 + 3][r] = v.w;
        }
        __syncthreads();

#pragma unroll
        for (int k = 0; k < GBK; k++) {
            float a[8], bf[4];
            *(float4*)&a[0] = *(const float4*)&As[k][ty * 8];
            *(float4*)&a[4] = *(const float4*)&As[k][ty * 8 + 4];
            *(float4*)&bf[0] = *(const float4*)&Bs[k][tx * 4];
#pragma unroll
            for (int i = 0; i < 8; i++)
#pragma unroll
                for (int j = 0; j < 4; j++) acc[i][j] += a[i] * bf[j];
        }
        __syncthreads();
    }

    // Epilogue
    float4 bv = *(const float4*)(bias + col0 + tx * 4);
#pragma unroll
    for (int i = 0; i < 8; i++) {
        int r = row0 + ty * 8 + i;
        int c = col0 + tx * 4;
        float4 v;
        v.x = acc[i][0] + bv.x;
        v.y = acc[i][1] + bv.y;
        v.z = acc[i][2] + bv.z;
        v.w = acc[i][3] + bv.w;
        if (ep == 1) {
            v.x = gelu_exact(v.x); v.y = gelu_exact(v.y);
            v.z = gelu_exact(v.z); v.w = gelu_exact(v.w);
        } else if (ep == 2) {
            float4 rv = *(const float4*)(resid + (size_t)r * Ndim + c);
            v.x += rv.x; v.y += rv.y; v.z += rv.z; v.w += rv.w;
        }
        *(float4*)(C + (size_t)r * Ndim + c) = v;
    }
}

// ---------------------------------------------------------------------------
// Flash-style causal attention. grid = (S/128, B*H), block = 128.
// Thread = one query row; keys staged in 16-row smem tiles; online softmax.
// ---------------------------------------------------------------------------
__global__ __launch_bounds__(128)
void attn_kernel(const float* __restrict__ Q,
                 const float* __restrict__ Kp,
                 const float* __restrict__ Vp,
                 float* __restrict__ CTX)
{
    __shared__ float Ks[16][32];
    __shared__ float Vs[16][32];

    const int qt  = blockIdx.x;
    const int bh  = blockIdx.y;
    const int b   = bh >> 3;
    const int hh  = bh & 7;
    const int tid = threadIdx.x;
    const int qi  = qt * 128 + tid;

    const size_t qbase = ((size_t)(b * Sc + qi)) * Dc + hh * DHc;

    float qreg[32];
#pragma unroll
    for (int i = 0; i < 8; i++) {
        float4 t4 = *(const float4*)(Q + qbase + i * 4);
        qreg[i * 4 + 0] = t4.x; qreg[i * 4 + 1] = t4.y;
        qreg[i * 4 + 2] = t4.z; qreg[i * 4 + 3] = t4.w;
    }
    float acc[32];
#pragma unroll
    for (int d = 0; d < 32; d++) acc[d] = 0.f;

    float mx = -1e30f, l = 0.f;
    const float scale = 0.17677669529663689f;   // 1/sqrt(32)

    const int lr = tid >> 3;          // 0..15 (key row in tile)
    const int lc = (tid & 7) * 4;     // 0..28 (dh col, float4)
    const int kend = (qt + 1) * 128;

    for (int kt = 0; kt < kend; kt += 16) {
        const size_t kb = ((size_t)(b * Sc + kt + lr)) * Dc + hh * DHc + lc;
        __syncthreads();  // protect previous tile reads
        *(float4*)&Ks[lr][lc] = *(const float4*)(Kp + kb);
        *(float4*)&Vs[lr][lc] = *(const float4*)(Vp + kb);
        __syncthreads();

        float sv[16];
        float tmax = -1e30f;
#pragma unroll
        for (int kk = 0; kk < 16; kk++) {
            float dot = 0.f;
#pragma unroll
            for (int d4 = 0; d4 < 8; d4++) {
                float4 kv = *(const float4*)&Ks[kk][d4 * 4];
                dot += qreg[d4 * 4 + 0] * kv.x + qreg[d4 * 4 + 1] * kv.y
                     + qreg[d4 * 4 + 2] * kv.z + qreg[d4 * 4 + 3] * kv.w;
            }
            bool valid = (kt + kk) <= qi;
            float s = valid ? dot * scale : -1e30f;
            sv[kk] = s;
            tmax = fmaxf(tmax, s);
        }
        float mnew = fmaxf(mx, tmax);
        float corr = __expf(mx - mnew);   // exp(-1e30 - x) underflows to 0 cleanly
        mx = mnew;
        l *= corr;
#pragma unroll
        for (int d = 0; d < 32; d++) acc[d] *= corr;

#pragma unroll
        for (int kk = 0; kk < 16; kk++) {
            float p = (sv[kk] > -1e29f) ? __expf(sv[kk] - mnew) : 0.f;
            l += p;
#pragma unroll
            for (int d4 = 0; d4 < 8; d4++) {
                float4 vv = *(const float4*)&Vs[kk][d4 * 4];
                acc[d4 * 4 + 0] += p * vv.x;
                acc[d4 * 4 + 1] += p * vv.y;
                acc[d4 * 4 + 2] += p * vv.z;
                acc[d4 * 4 + 3] += p * vv.w;
            }
        }
    }

    const float inv = 1.f / l;
#pragma unroll
    for (int i = 0; i < 8; i++) {
        float4 o4 = make_float4(acc[i * 4 + 0] * inv, acc[i * 4 + 1] * inv,
                                acc[i * 4 + 2] * inv, acc[i * 4 + 3] * inv);
        *(float4*)(CTX + qbase + i * 4) = o4;
    }
}

// ---------------------------------------------------------------------------
// LayerNorm over last dim (256). One block (256 threads) per row. Two-pass.
// ---------------------------------------------------------------------------
__global__ __launch_bounds__(256)
void ln_kernel(const float* __restrict__ X,
               const float* __restrict__ gw,
               const float* __restrict__ bw,
               float* __restrict__ Y)
{
    const int row = blockIdx.x;
    const int d   = threadIdx.x;
    __shared__ float red[8];
    __shared__ float bc;

    float v = X[(size_t)row * Dc + d];

    // pass 1: mean
    float s = v;
#pragma unroll
    for (int o = 16; o > 0; o >>= 1) s += __shfl_down_sync(0xffffffffu, s, o);
    if ((d & 31) == 0) red[d >> 5] = s;
    __syncthreads();
    if (d == 0) {
        float t = 0.f;
#pragma unroll
        for (int i = 0; i < 8; i++) t += red[i];
        bc = t * (1.0f / Dc);
    }
    __syncthreads();
    const float m  = bc;
    const float dv = v - m;

    // pass 2: variance of (x - m)
    float s2 = dv * dv;
#pragma unroll
    for (int o = 16; o > 0; o >>= 1) s2 += __shfl_down_sync(0xffffffffu, s2, o);
    __syncthreads();                    // everyone has read bc; safe to reuse
    if ((d & 31) == 0) red[d >> 5] = s2;
    __syncthreads();
    if (d == 0) {
        float t = 0.f;
#pragma unroll
        for (int i = 0; i < 8; i++) t += red[i];
        bc = t * (1.0f / Dc);
    }
    __syncthreads();
    const float var = bc;

    Y[(size_t)row * Dc + d] = gw[d] * dv * rsqrtf(var + 1e-12f) + bw[d];
}

// ---------------------------------------------------------------------------
// Output projection: logits[t,m] = h[t,:] . out_w[m,:] + out_b[m]   (M=4)
// One warp per token; 8 warps per block.
// ---------------------------------------------------------------------------
__global__ __launch_bounds__(256)
void outproj_kernel(const float* __restrict__ ow,
                    const float* __restrict__ ob,
                    float* __restrict__ out)
{
    const int w    = threadIdx.x >> 5;
    const int lane = threadIdx.x & 31;
    const int t    = blockIdx.x * 8 + w;
    const float* hr = g_h + (size_t)t * Dc;

    float hv[8];
#pragma unroll
    for (int i = 0; i < 8; i++) hv[i] = hr[lane + 32 * i];

#pragma unroll
    for (int m = 0; m < Mc; m++) {
        const float* wr = ow + m * Dc;
        float p = 0.f;
#pragma unroll
        for (int i = 0; i < 8; i++) p += hv[i] * wr[lane + 32 * i];
#pragma unroll
        for (int o = 16; o > 0; o >>= 1) p += __shfl_down_sync(0xffffffffu, p, o);
        if (lane == 0) out[t * Mc + m] = p + ob[m];
    }
}

// ---------------------------------------------------------------------------
// Host orchestration (graph-capturable: kernel launches only)
// ---------------------------------------------------------------------------
extern "C" void kernel_launch(void* const* d_in, const int* in_sizes, int n_in,
                              void* d_out, int out_size)
{
    const int*   x     = (const int*)  d_in[0];
    const float* emb   = (const float*)d_in[1];
    const float* pe    = (const float*)d_in[2];
    const float* q_w   = (const float*)d_in[3];
    const float* q_b   = (const float*)d_in[4];
    const float* k_w   = (const float*)d_in[5];
    const float* k_b   = (const float*)d_in[6];
    const float* v_w   = (const float*)d_in[7];
    const float* v_b   = (const float*)d_in[8];
    const float* o_w   = (const float*)d_in[9];
    const float* o_b   = (const float*)d_in[10];
    const float* ln1_g = (const float*)d_in[11];
    const float* ln1_b = (const float*)d_in[12];
    const float* f1_w  = (const float*)d_in[13];
    const float* f1_b  = (const float*)d_in[14];
    const float* f2_w  = (const float*)d_in[15];
    const float* f2_b  = (const float*)d_in[16];
    const float* ln2_g = (const float*)d_in[17];
    const float* ln2_b = (const float*)d_in[18];
    const float* out_w = (const float*)d_in[19];
    const float* out_b = (const float*)d_in[20];
    float* out = (float*)d_out;

    float *h, *q, *k, *v, *ctx, *tmp, *ao, *ff;
    cudaGetSymbolAddress((void**)&h,   g_h);
    cudaGetSymbolAddress((void**)&q,   g_q);
    cudaGetSymbolAddress((void**)&k,   g_k);
    cudaGetSymbolAddress((void**)&v,   g_v);
    cudaGetSymbolAddress((void**)&ctx, g_ctx);
    cudaGetSymbolAddress((void**)&tmp, g_tmp);
    cudaGetSymbolAddress((void**)&ao,  g_ao);
    cudaGetSymbolAddress((void**)&ff,  g_ff);

    embed_kernel<<<TOK * Dc / 256, 256>>>(x, emb, pe);

    const dim3 gD(Dc / GBN, TOK / GBM);   // N=256 GEMMs:  (4, 64)
    const dim3 gI(Ic / GBN, TOK / GBM);   // N=1024 GEMM:  (16, 64)
    const dim3 gAttn(Sc / 128, Bc * Hc);  // (8, 64)

    for (int l = 0; l < Lc; l++) {
        const size_t wo  = (size_t)l * Dc * Dc;
        const size_t bo  = (size_t)l * Dc;
        const size_t f1o = (size_t)l * Ic * Dc;

        gemm_kernel<<<gD, 256>>>(h, q_w + wo, q_b + bo, nullptr, q, Dc, Dc, 0);
        gemm_kernel<<<gD, 256>>>(h, k_w + wo, k_b + bo, nullptr, k, Dc, Dc, 0);
        gemm_kernel<<<gD, 256>>>(h, v_w + wo, v_b + bo, nullptr, v, Dc, Dc, 0);

        attn_kernel<<<gAttn, 128>>>(q, k, v, ctx);

        // tmp = ctx @ o_w^T + o_b + h ; ao = LN1(tmp)
        gemm_kernel<<<gD, 256>>>(ctx, o_w + wo, o_b + bo, h, tmp, Dc, Dc, 2);
        ln_kernel<<<TOK, 256>>>(tmp, ln1_g + bo, ln1_b + bo, ao);

        // ff = gelu(ao @ f1^T + f1_b)
        gemm_kernel<<<gI, 256>>>(ao, f1_w + f1o, f1_b + (size_t)l * Ic, nullptr, ff, Ic, Dc, 1);
        // tmp = ff @ f2^T + f2_b + ao ; h = LN2(tmp)
        gemm_kernel<<<gD, 256>>>(ff, f2_w + f1o, f2_b + bo, ao, tmp, Dc, Ic, 2);
        ln_kernel<<<TOK, 256>>>(tmp, ln2_g + bo, ln2_b + bo, h);
    }

    outproj_kernel<<<TOK / 8, 256>>>(out_w, out_b, out);
}

// round 13
// speedup vs baseline: 1.1601x; 1.1581x over previous
#include <cuda_runtime.h>
#include <cuda_bf16.h>
#include <math.h>
#include <stdint.h>

#define Lc  4
#define Bc  8
#define Sc  1024
#define Dc  256
#define Hc  8
#define DHc 32
#define Ic  1024
#define Mc  4
#define TOK 8192

// ---------------------------------------------------------------------------
// Scratch (__device__ globals; no allocations allowed)
// ---------------------------------------------------------------------------
__device__ float g_h  [TOK*Dc];
__device__ float g_q  [TOK*Dc];
__device__ float g_k  [TOK*Dc];
__device__ float g_v  [TOK*Dc];
__device__ float g_ctx[TOK*Dc];
__device__ float g_tmp[TOK*Dc];
__device__ float g_ao [TOK*Dc];
__device__ float g_ff [TOK*Ic];
__device__ __nv_bfloat16 g_a3[TOK*3*Ic];      // bf16x3 activations, max pitch 3072
__device__ __nv_bfloat16 g_w3[Lc*2359296ull]; // bf16x3 weights per layer

__device__ __forceinline__ float gelu_exact(float v) {
    return 0.5f * v * (1.0f + erff(v * 0.70710678118654752f));
}

// ---------------------------------------------------------------------------
// bf16x3 conversion: activations [hi|lo|hi], weights [hi|hi|lo]
// ---------------------------------------------------------------------------
__global__ __launch_bounds__(256)
void conva_kernel(const float* __restrict__ src, __nv_bfloat16* __restrict__ dst, int K)
{
    int gid = blockIdx.x * 256 + threadIdx.x;  // over M*K/2
    int k2 = K >> 1;
    int t = gid / k2;
    int k = (gid - t * k2) * 2;
    float2 v = *(const float2*)(src + (size_t)t * K + k);
    __nv_bfloat16 h0 = __float2bfloat16(v.x);
    __nv_bfloat16 h1 = __float2bfloat16(v.y);
    __nv_bfloat16 l0 = __float2bfloat16(v.x - __bfloat162float(h0));
    __nv_bfloat16 l1 = __float2bfloat16(v.y - __bfloat162float(h1));
    __nv_bfloat162 hh; hh.x = h0; hh.y = h1;
    __nv_bfloat162 ll; ll.x = l0; ll.y = l1;
    __nv_bfloat16* d = dst + (size_t)t * 3 * K;
    *(__nv_bfloat162*)(d + k)         = hh;
    *(__nv_bfloat162*)(d + K + k)     = ll;
    *(__nv_bfloat162*)(d + 2 * K + k) = hh;
}

__global__ __launch_bounds__(256)
void convw_kernel(const float* __restrict__ src, __nv_bfloat16* __restrict__ dst, int K)
{
    int gid = blockIdx.x * 256 + threadIdx.x;  // over N*K/2
    int k2 = K >> 1;
    int n = gid / k2;
    int k = (gid - n * k2) * 2;
    float2 v = *(const float2*)(src + (size_t)n * K + k);
    __nv_bfloat16 h0 = __float2bfloat16(v.x);
    __nv_bfloat16 h1 = __float2bfloat16(v.y);
    __nv_bfloat16 l0 = __float2bfloat16(v.x - __bfloat162float(h0));
    __nv_bfloat16 l1 = __float2bfloat16(v.y - __bfloat162float(h1));
    __nv_bfloat162 hh; hh.x = h0; hh.y = h1;
    __nv_bfloat162 ll; ll.x = l0; ll.y = l1;
    __nv_bfloat16* d = dst + (size_t)n * 3 * K;
    *(__nv_bfloat162*)(d + k)         = hh;
    *(__nv_bfloat162*)(d + K + k)     = hh;
    *(__nv_bfloat162*)(d + 2 * K + k) = ll;
}

// ---------------------------------------------------------------------------
// HMMA GEMM: out[8192,N] = A3[8192,K3] @ W3[N,K3]^T + bias (+gelu / +resid)
// CTA tile 128x128, 8 warps (4m x 2n), warp tile 32x64 (2x8 mma.m16n8k16).
// bf16 in, fp32 accum. Double-buffered smem, pad-40 rows (conflict-free).
//   ep=0 bias only; ep=1 gelu(bias+acc); ep=2 bias+acc+resid
// ---------------------------------------------------------------------------
#define SPAD 40

__global__ __launch_bounds__(256)
void gemm3_kernel(const __nv_bfloat16* __restrict__ A3,
                  const __nv_bfloat16* __restrict__ W3,
                  const float* __restrict__ bias,
                  const float* __restrict__ resid,
                  float* __restrict__ outp,
                  int Ndim, int K3, int ep)
{
    __shared__ __align__(16) __nv_bfloat16 smA[2][128][SPAD];
    __shared__ __align__(16) __nv_bfloat16 smB[2][128][SPAD];

    const int tid  = threadIdx.x;
    const int wid  = tid >> 5;
    const int lane = tid & 31;
    const int g    = lane >> 2;     // groupID 0..7
    const int t2   = (lane & 3) * 2;// threadID_in_group * 2
    const int wm   = wid >> 1;      // 0..3  (rows wm*32)
    const int wn   = wid & 1;       // 0..1  (cols wn*64)

    const int row0 = blockIdx.y * 128;
    const int col0 = blockIdx.x * 128;

    // global->smem load mapping: uint4 (8 bf16); row pitch in tile = 4 uint4
    const int lr = tid >> 2;          // 0..63
    const int lc = (tid & 3) * 8;     // 0,8,16,24
    const __nv_bfloat16* gA0 = A3 + (size_t)(row0 + lr)      * K3 + lc;
    const __nv_bfloat16* gA1 = A3 + (size_t)(row0 + lr + 64) * K3 + lc;
    const __nv_bfloat16* gB0 = W3 + (size_t)(col0 + lr)      * K3 + lc;
    const __nv_bfloat16* gB1 = W3 + (size_t)(col0 + lr + 64) * K3 + lc;

    float acc[2][8][4];
#pragma unroll
    for (int i = 0; i < 2; i++)
#pragma unroll
        for (int j = 0; j < 8; j++)
#pragma unroll
            for (int c = 0; c < 4; c++) acc[i][j][c] = 0.f;

    const int nc = K3 >> 5;   // chunks of 32 bf16

    // prologue: chunk 0 -> buf 0
    {
        uint4 a0 = *(const uint4*)gA0;
        uint4 a1 = *(const uint4*)gA1;
        uint4 b0 = *(const uint4*)gB0;
        uint4 b1 = *(const uint4*)gB1;
        *(uint4*)&smA[0][lr][lc]      = a0;
        *(uint4*)&smA[0][lr + 64][lc] = a1;
        *(uint4*)&smB[0][lr][lc]      = b0;
        *(uint4*)&smB[0][lr + 64][lc] = b1;
    }
    __syncthreads();

    for (int i = 0; i < nc; i++) {
        const int buf = i & 1;
        uint4 pa0, pa1, pb0, pb1;
        const bool more = (i + 1 < nc);
        if (more) {
            const int ko = (i + 1) * 32;
            pa0 = *(const uint4*)(gA0 + ko);
            pa1 = *(const uint4*)(gA1 + ko);
            pb0 = *(const uint4*)(gB0 + ko);
            pb1 = *(const uint4*)(gB1 + ko);
        }

        // compute chunk i
#pragma unroll
        for (int kk = 0; kk < 32; kk += 16) {
            uint32_t af[2][4];
#pragma unroll
            for (int mi = 0; mi < 2; mi++) {
                const __nv_bfloat16* ap = &smA[buf][wm * 32 + mi * 16 + g][kk + t2];
                af[mi][0] = *(const uint32_t*)(ap);
                af[mi][1] = *(const uint32_t*)(ap + 8 * SPAD);
                af[mi][2] = *(const uint32_t*)(ap + 8);
                af[mi][3] = *(const uint32_t*)(ap + 8 * SPAD + 8);
            }
#pragma unroll
            for (int ni = 0; ni < 8; ni++) {
                const __nv_bfloat16* bp = &smB[buf][wn * 64 + ni * 8 + g][kk + t2];
                uint32_t b0 = *(const uint32_t*)(bp);
                uint32_t b1 = *(const uint32_t*)(bp + 8);
#pragma unroll
                for (int mi = 0; mi < 2; mi++) {
                    asm volatile(
                        "mma.sync.aligned.m16n8k16.row.col.f32.bf16.bf16.f32 "
                        "{%0,%1,%2,%3}, {%4,%5,%6,%7}, {%8,%9}, {%0,%1,%2,%3};"
                        : "+f"(acc[mi][ni][0]), "+f"(acc[mi][ni][1]),
                          "+f"(acc[mi][ni][2]), "+f"(acc[mi][ni][3])
                        : "r"(af[mi][0]), "r"(af[mi][1]),
                          "r"(af[mi][2]), "r"(af[mi][3]),
                          "r"(b0), "r"(b1));
                }
            }
        }

        if (more) {
            __syncthreads();   // all compute on buf^1 from iter i-1 done
            const int nb = buf ^ 1;
            *(uint4*)&smA[nb][lr][lc]      = pa0;
            *(uint4*)&smA[nb][lr + 64][lc] = pa1;
            *(uint4*)&smB[nb][lr][lc]      = pb0;
            *(uint4*)&smB[nb][lr + 64][lc] = pb1;
            __syncthreads();
        }
    }

    // epilogue
#pragma unroll
    for (int mi = 0; mi < 2; mi++) {
        const int r0g = row0 + wm * 32 + mi * 16 + g;
#pragma unroll
        for (int ni = 0; ni < 8; ni++) {
            const int c = col0 + wn * 64 + ni * 8 + t2;
            const float b0 = bias[c], b1 = bias[c + 1];
            float2 v0, v1;
            v0.x = acc[mi][ni][0] + b0;  v0.y = acc[mi][ni][1] + b1;
            v1.x = acc[mi][ni][2] + b0;  v1.y = acc[mi][ni][3] + b1;
            if (ep == 1) {
                v0.x = gelu_exact(v0.x); v0.y = gelu_exact(v0.y);
                v1.x = gelu_exact(v1.x); v1.y = gelu_exact(v1.y);
            } else if (ep == 2) {
                float2 r0v = *(const float2*)(resid + (size_t)r0g * Ndim + c);
                float2 r1v = *(const float2*)(resid + (size_t)(r0g + 8) * Ndim + c);
                v0.x += r0v.x; v0.y += r0v.y;
                v1.x += r1v.x; v1.y += r1v.y;
            }
            *(float2*)(outp + (size_t)r0g * Ndim + c)       = v0;
            *(float2*)(outp + (size_t)(r0g + 8) * Ndim + c) = v1;
        }
    }
}

// ---------------------------------------------------------------------------
// Embedding + positional encoding
// ---------------------------------------------------------------------------
__global__ void embed_kernel(const int* __restrict__ x,
                             const float* __restrict__ emb,
                             const float* __restrict__ pe)
{
    int gid = blockIdx.x * 256 + threadIdx.x;
    int t = gid >> 8;
    int d = gid & 255;
    g_h[gid] = emb[x[t] * Dc + d] + pe[(t & (Sc - 1)) * Dc + d];
}

// ---------------------------------------------------------------------------
// Flash-style causal attention (validated fp32)
// ---------------------------------------------------------------------------
__global__ __launch_bounds__(128)
void attn_kernel(const float* __restrict__ Q,
                 const float* __restrict__ Kp,
                 const float* __restrict__ Vp,
                 float* __restrict__ CTX)
{
    __shared__ float Ks[16][32];
    __shared__ float Vs[16][32];

    const int qt  = blockIdx.x;
    const int bh  = blockIdx.y;
    const int b   = bh >> 3;
    const int hh  = bh & 7;
    const int tid = threadIdx.x;
    const int qi  = qt * 128 + tid;
    const size_t qbase = ((size_t)(b * Sc + qi)) * Dc + hh * DHc;

    float qreg[32];
#pragma unroll
    for (int i = 0; i < 8; i++) {
        float4 t4 = *(const float4*)(Q + qbase + i * 4);
        qreg[i*4+0]=t4.x; qreg[i*4+1]=t4.y; qreg[i*4+2]=t4.z; qreg[i*4+3]=t4.w;
    }
    float acc[32];
#pragma unroll
    for (int d = 0; d < 32; d++) acc[d] = 0.f;

    float mx = -1e30f, l = 0.f;
    const float scale = 0.17677669529663689f;
    const int lr = tid >> 3;
    const int lc = (tid & 7) * 4;
    const int kend = (qt + 1) * 128;

    for (int kt = 0; kt < kend; kt += 16) {
        const size_t kb = ((size_t)(b * Sc + kt + lr)) * Dc + hh * DHc + lc;
        __syncthreads();
        *(float4*)&Ks[lr][lc] = *(const float4*)(Kp + kb);
        *(float4*)&Vs[lr][lc] = *(const float4*)(Vp + kb);
        __syncthreads();

        float sv[16];
        float tmax = -1e30f;
#pragma unroll
        for (int kk = 0; kk < 16; kk++) {
            float dot = 0.f;
#pragma unroll
            for (int d4 = 0; d4 < 8; d4++) {
                float4 kv = *(const float4*)&Ks[kk][d4 * 4];
                dot += qreg[d4*4+0]*kv.x + qreg[d4*4+1]*kv.y
                     + qreg[d4*4+2]*kv.z + qreg[d4*4+3]*kv.w;
            }
            bool valid = (kt + kk) <= qi;
            float s = valid ? dot * scale : -1e30f;
            sv[kk] = s;
            tmax = fmaxf(tmax, s);
        }
        float mnew = fmaxf(mx, tmax);
        float corr = __expf(mx - mnew);
        mx = mnew;
        l *= corr;
#pragma unroll
        for (int d = 0; d < 32; d++) acc[d] *= corr;

#pragma unroll
        for (int kk = 0; kk < 16; kk++) {
            float p = (sv[kk] > -1e29f) ? __expf(sv[kk] - mnew) : 0.f;
            l += p;
#pragma unroll
            for (int d4 = 0; d4 < 8; d4++) {
                float4 vv = *(const float4*)&Vs[kk][d4 * 4];
                acc[d4*4+0] += p*vv.x; acc[d4*4+1] += p*vv.y;
                acc[d4*4+2] += p*vv.z; acc[d4*4+3] += p*vv.w;
            }
        }
    }
    const float inv = 1.f / l;
#pragma unroll
    for (int i = 0; i < 8; i++) {
        float4 o4 = make_float4(acc[i*4+0]*inv, acc[i*4+1]*inv,
                                acc[i*4+2]*inv, acc[i*4+3]*inv);
        *(float4*)(CTX + qbase + i * 4) = o4;
    }
}

// ---------------------------------------------------------------------------
// LayerNorm (256 threads per row)
// ---------------------------------------------------------------------------
__global__ __launch_bounds__(256)
void ln_kernel(const float* __restrict__ X,
               const float* __restrict__ gw,
               const float* __restrict__ bw,
               float* __restrict__ Y)
{
    const int row = blockIdx.x;
    const int d   = threadIdx.x;
    __shared__ float red[8];
    __shared__ float bc;

    float v = X[(size_t)row * Dc + d];
    float s = v;
#pragma unroll
    for (int o = 16; o > 0; o >>= 1) s += __shfl_down_sync(0xffffffffu, s, o);
    if ((d & 31) == 0) red[d >> 5] = s;
    __syncthreads();
    if (d == 0) {
        float t = 0.f;
#pragma unroll
        for (int i = 0; i < 8; i++) t += red[i];
        bc = t * (1.0f / Dc);
    }
    __syncthreads();
    const float m  = bc;
    const float dv = v - m;

    float s2 = dv * dv;
#pragma unroll
    for (int o = 16; o > 0; o >>= 1) s2 += __shfl_down_sync(0xffffffffu, s2, o);
    __syncthreads();
    if ((d & 31) == 0) red[d >> 5] = s2;
    __syncthreads();
    if (d == 0) {
        float t = 0.f;
#pragma unroll
        for (int i = 0; i < 8; i++) t += red[i];
        bc = t * (1.0f / Dc);
    }
    __syncthreads();
    Y[(size_t)row * Dc + d] = gw[d] * dv * rsqrtf(bc + 1e-12f) + bw[d];
}

// ---------------------------------------------------------------------------
// Output projection (M=4)
// ---------------------------------------------------------------------------
__global__ __launch_bounds__(256)
void outproj_kernel(const float* __restrict__ ow,
                    const float* __restrict__ ob,
                    float* __restrict__ out)
{
    const int w    = threadIdx.x >> 5;
    const int lane = threadIdx.x & 31;
    const int t    = blockIdx.x * 8 + w;
    const float* hr = g_h + (size_t)t * Dc;

    float hv[8];
#pragma unroll
    for (int i = 0; i < 8; i++) hv[i] = hr[lane + 32 * i];

#pragma unroll
    for (int m = 0; m < Mc; m++) {
        const float* wr = ow + m * Dc;
        float p = 0.f;
#pragma unroll
        for (int i = 0; i < 8; i++) p += hv[i] * wr[lane + 32 * i];
#pragma unroll
        for (int o = 16; o > 0; o >>= 1) p += __shfl_down_sync(0xffffffffu, p, o);
        if (lane == 0) out[t * Mc + m] = p + ob[m];
    }
}

// ---------------------------------------------------------------------------
// Host orchestration (graph-capturable)
// ---------------------------------------------------------------------------
extern "C" void kernel_launch(void* const* d_in, const int* in_sizes, int n_in,
                              void* d_out, int out_size)
{
    const int*   x     = (const int*)  d_in[0];
    const float* emb   = (const float*)d_in[1];
    const float* pe    = (const float*)d_in[2];
    const float* q_w   = (const float*)d_in[3];
    const float* q_b   = (const float*)d_in[4];
    const float* k_w   = (const float*)d_in[5];
    const float* k_b   = (const float*)d_in[6];
    const float* v_w   = (const float*)d_in[7];
    const float* v_b   = (const float*)d_in[8];
    const float* o_w   = (const float*)d_in[9];
    const float* o_b   = (const float*)d_in[10];
    const float* ln1_g = (const float*)d_in[11];
    const float* ln1_b = (const float*)d_in[12];
    const float* f1_w  = (const float*)d_in[13];
    const float* f1_b  = (const float*)d_in[14];
    const float* f2_w  = (const float*)d_in[15];
    const float* f2_b  = (const float*)d_in[16];
    const float* ln2_g = (const float*)d_in[17];
    const float* ln2_b = (const float*)d_in[18];
    const float* out_w = (const float*)d_in[19];
    const float* out_b = (const float*)d_in[20];
    float* out = (float*)d_out;

    float *h, *q, *k, *v, *ctx, *tmp, *ao, *ff;
    __nv_bfloat16 *a3, *w3;
    cudaGetSymbolAddress((void**)&h,   g_h);
    cudaGetSymbolAddress((void**)&q,   g_q);
    cudaGetSymbolAddress((void**)&k,   g_k);
    cudaGetSymbolAddress((void**)&v,   g_v);
    cudaGetSymbolAddress((void**)&ctx, g_ctx);
    cudaGetSymbolAddress((void**)&tmp, g_tmp);
    cudaGetSymbolAddress((void**)&ao,  g_ao);
    cudaGetSymbolAddress((void**)&ff,  g_ff);
    cudaGetSymbolAddress((void**)&a3,  g_a3);
    cudaGetSymbolAddress((void**)&w3,  g_w3);

    // weight -> bf16x3 conversion (deterministic; part of the graph)
    for (int l = 0; l < Lc; l++) {
        size_t wb = (size_t)l * 2359296ull;
        convw_kernel<<<128, 256>>>(q_w  + (size_t)l * 65536,  w3 + wb,           Dc);
        convw_kernel<<<128, 256>>>(k_w  + (size_t)l * 65536,  w3 + wb + 196608,  Dc);
        convw_kernel<<<128, 256>>>(v_w  + (size_t)l * 65536,  w3 + wb + 393216,  Dc);
        convw_kernel<<<128, 256>>>(o_w  + (size_t)l * 65536,  w3 + wb + 589824,  Dc);
        convw_kernel<<<512, 256>>>(f1_w + (size_t)l * 262144, w3 + wb + 786432,  Dc);
        convw_kernel<<<512, 256>>>(f2_w + (size_t)l * 262144, w3 + wb + 1572864, Ic);
    }

    embed_kernel<<<TOK * Dc / 256, 256>>>(x, emb, pe);

    const dim3 gN2(2, 64);        // N=256 GEMMs  (CTA tile 128x128)
    const dim3 gN8(8, 64);        // N=1024 GEMM
    const dim3 gAttn(Sc / 128, Bc * Hc);

    for (int l = 0; l < Lc; l++) {
        const size_t wb = (size_t)l * 2359296ull;
        const size_t bo = (size_t)l * Dc;

        conva_kernel<<<4096, 256>>>(h, a3, Dc);
        gemm3_kernel<<<gN2, 256>>>(a3, w3 + wb,          q_b + bo, nullptr, q, Dc, 768, 0);
        gemm3_kernel<<<gN2, 256>>>(a3, w3 + wb + 196608, k_b + bo, nullptr, k, Dc, 768, 0);
        gemm3_kernel<<<gN2, 256>>>(a3, w3 + wb + 393216, v_b + bo, nullptr, v, Dc, 768, 0);

        attn_kernel<<<gAttn, 128>>>(q, k, v, ctx);

        conva_kernel<<<4096, 256>>>(ctx, a3, Dc);
        gemm3_kernel<<<gN2, 256>>>(a3, w3 + wb + 589824, o_b + bo, h, tmp, Dc, 768, 2);
        ln_kernel<<<TOK, 256>>>(tmp, ln1_g + bo, ln1_b + bo, ao);

        conva_kernel<<<4096, 256>>>(ao, a3, Dc);
        gemm3_kernel<<<gN8, 256>>>(a3, w3 + wb + 786432, f1_b + (size_t)l * Ic,
                                   nullptr, ff, Ic, 768, 1);
        conva_kernel<<<16384, 256>>>(ff, a3, Ic);
        gemm3_kernel<<<gN2, 256>>>(a3, w3 + wb + 1572864, f2_b + bo, ao, tmp, Dc, 3072, 2);
        ln_kernel<<<TOK, 256>>>(tmp, ln2_g + bo, ln2_b + bo, h);
    }

    outproj_kernel<<<TOK / 8, 256>>>(out_w, out_b, out);
}

// round 14
// speedup vs baseline: 2.1990x; 1.8956x over previous
#include <cuda_runtime.h>
#include <cuda_bf16.h>
#include <math.h>
#include <stdint.h>

#define Lc  4
#define Bc  8
#define Sc  1024
#define Dc  256
#define Hc  8
#define DHc 32
#define Ic  1024
#define Mc  4
#define TOK 8192
#define LWS 2359296ull   // per-layer stride in g_w3

// ---------------------------------------------------------------------------
// Scratch (__device__ globals; no allocations allowed)
// ---------------------------------------------------------------------------
__device__ float g_h  [TOK*Dc];
__device__ float g_tmp[TOK*Dc];
__device__ float g_ao [TOK*Dc];
__device__ __nv_bfloat16 g_qb [TOK*Dc];
__device__ __nv_bfloat16 g_kb [TOK*Dc];
__device__ __nv_bfloat16 g_vb [TOK*Dc];
__device__ __nv_bfloat16 g_vt [TOK*Dc];        // [(b*256+d)][s]
__device__ __nv_bfloat16 g_a3 [TOK*3*Dc];      // [hi|lo|hi] pitch 768
__device__ __nv_bfloat16 g_a3c[TOK*3*Dc];      // ctx bf16x3
__device__ __nv_bfloat16 g_a3f[TOK*3*Ic];      // ff bf16x3 pitch 3072
__device__ __nv_bfloat16 g_w3 [Lc*LWS];        // [hi|hi|lo] weights

__device__ __forceinline__ float gelu_exact(float v) {
    return 0.5f * v * (1.0f + erff(v * 0.70710678118654752f));
}

// Fast exp on FMA pipe (no MUFU): exp(x)=2^(x*log2e), Taylor deg-4 on [-.5,.5]
__device__ __forceinline__ float fexp(float x) {
    float y = fmaxf(x * 1.4426950408889634f, -125.0f);
    float t = y + 12582912.0f;                 // round-to-nearest magic
    int   k = __float_as_int(t) - 0x4B400000;
    float f = y - (t - 12582912.0f);           // frac in [-0.5, 0.5]
    float p = 9.6181294e-3f;
    p = fmaf(p, f, 5.5504109e-2f);
    p = fmaf(p, f, 2.4022651e-1f);
    p = fmaf(p, f, 6.9314718e-1f);
    p = fmaf(p, f, 1.0f);
    return __int_as_float(__float_as_int(p) + (k << 23));
}

__device__ __forceinline__ uint32_t bf2u32(float a, float b) {
    __nv_bfloat162 t;
    t.x = __float2bfloat16(a);
    t.y = __float2bfloat16(b);
    return *(uint32_t*)&t;
}

// ---------------------------------------------------------------------------
// Weight -> bf16x3 [hi|hi|lo], all Lc layers in one launch per weight type
// ---------------------------------------------------------------------------
__global__ __launch_bounds__(256)
void convw_kernel(const float* __restrict__ src, __nv_bfloat16* __restrict__ dst,
                  int K, int Nper)
{
    int gid = blockIdx.x * 256 + threadIdx.x;   // Lc*Nper*K/2
    int kh = K >> 1;
    int l  = gid / (Nper * kh);
    int rem = gid - l * (Nper * kh);
    int n  = rem / kh;
    int k  = (rem - n * kh) * 2;
    float2 v = *(const float2*)(src + ((size_t)l * Nper + n) * K + k);
    __nv_bfloat16 h0 = __float2bfloat16(v.x);
    __nv_bfloat16 h1 = __float2bfloat16(v.y);
    __nv_bfloat162 hh; hh.x = h0; hh.y = h1;
    __nv_bfloat162 ll;
    ll.x = __float2bfloat16(v.x - __bfloat162float(h0));
    ll.y = __float2bfloat16(v.y - __bfloat162float(h1));
    __nv_bfloat16* d = dst + (size_t)l * LWS + (size_t)n * 3 * K;
    *(__nv_bfloat162*)(d + k)         = hh;
    *(__nv_bfloat162*)(d + K + k)     = hh;
    *(__nv_bfloat162*)(d + 2 * K + k) = ll;
}

// ---------------------------------------------------------------------------
// HMMA GEMM: out[8192,N] = A3[8192,K3] @ W3[N,K3]^T + bias
//   ep=1: gelu -> bf16x3 (obf, pitch 3*Ndim)
//   ep=2: +resid -> fp32 (outp)
//   ep=3: -> bf16 (obf, pitch Ndim)
// ---------------------------------------------------------------------------
#define SPAD 40

__global__ __launch_bounds__(256)
void gemm3_kernel(const __nv_bfloat16* __restrict__ A3,
                  const __nv_bfloat16* __restrict__ W3,
                  const float* __restrict__ bias,
                  const float* __restrict__ resid,
                  float* __restrict__ outp,
                  __nv_bfloat16* __restrict__ obf,
                  int Ndim, int K3, int ep)
{
    __shared__ __align__(16) __nv_bfloat16 smA[2][128][SPAD];
    __shared__ __align__(16) __nv_bfloat16 smB[2][128][SPAD];

    const int tid  = threadIdx.x;
    const int wid  = tid >> 5;
    const int lane = tid & 31;
    const int g    = lane >> 2;
    const int t2   = (lane & 3) * 2;
    const int wm   = wid >> 1;
    const int wn   = wid & 1;

    const int row0 = blockIdx.y * 128;
    const int col0 = blockIdx.x * 128;

    const int lr = tid >> 2;
    const int lc = (tid & 3) * 8;
    const __nv_bfloat16* gA0 = A3 + (size_t)(row0 + lr)      * K3 + lc;
    const __nv_bfloat16* gA1 = A3 + (size_t)(row0 + lr + 64) * K3 + lc;
    const __nv_bfloat16* gB0 = W3 + (size_t)(col0 + lr)      * K3 + lc;
    const __nv_bfloat16* gB1 = W3 + (size_t)(col0 + lr + 64) * K3 + lc;

    float acc[2][8][4];
#pragma unroll
    for (int i = 0; i < 2; i++)
#pragma unroll
        for (int j = 0; j < 8; j++)
#pragma unroll
            for (int c = 0; c < 4; c++) acc[i][j][c] = 0.f;

    const int nc = K3 >> 5;

    {
        *(uint4*)&smA[0][lr][lc]      = *(const uint4*)gA0;
        *(uint4*)&smA[0][lr + 64][lc] = *(const uint4*)gA1;
        *(uint4*)&smB[0][lr][lc]      = *(const uint4*)gB0;
        *(uint4*)&smB[0][lr + 64][lc] = *(const uint4*)gB1;
    }
    __syncthreads();

    for (int i = 0; i < nc; i++) {
        const int buf = i & 1;
        uint4 pa0, pa1, pb0, pb1;
        const bool more = (i + 1 < nc);
        if (more) {
            const int ko = (i + 1) * 32;
            pa0 = *(const uint4*)(gA0 + ko);
            pa1 = *(const uint4*)(gA1 + ko);
            pb0 = *(const uint4*)(gB0 + ko);
            pb1 = *(const uint4*)(gB1 + ko);
        }

#pragma unroll
        for (int kk = 0; kk < 32; kk += 16) {
            uint32_t af[2][4];
#pragma unroll
            for (int mi = 0; mi < 2; mi++) {
                const __nv_bfloat16* ap = &smA[buf][wm * 32 + mi * 16 + g][kk + t2];
                af[mi][0] = *(const uint32_t*)(ap);
                af[mi][1] = *(const uint32_t*)(ap + 8 * SPAD);
                af[mi][2] = *(const uint32_t*)(ap + 8);
                af[mi][3] = *(const uint32_t*)(ap + 8 * SPAD + 8);
            }
#pragma unroll
            for (int ni = 0; ni < 8; ni++) {
                const __nv_bfloat16* bp = &smB[buf][wn * 64 + ni * 8 + g][kk + t2];
                uint32_t b0 = *(const uint32_t*)(bp);
                uint32_t b1 = *(const uint32_t*)(bp + 8);
#pragma unroll
                for (int mi = 0; mi < 2; mi++) {
                    asm volatile(
                        "mma.sync.aligned.m16n8k16.row.col.f32.bf16.bf16.f32 "
                        "{%0,%1,%2,%3}, {%4,%5,%6,%7}, {%8,%9}, {%0,%1,%2,%3};"
                        : "+f"(acc[mi][ni][0]), "+f"(acc[mi][ni][1]),
                          "+f"(acc[mi][ni][2]), "+f"(acc[mi][ni][3])
                        : "r"(af[mi][0]), "r"(af[mi][1]),
                          "r"(af[mi][2]), "r"(af[mi][3]),
                          "r"(b0), "r"(b1));
                }
            }
        }

        if (more) {
            __syncthreads();
            const int nb = buf ^ 1;
            *(uint4*)&smA[nb][lr][lc]      = pa0;
            *(uint4*)&smA[nb][lr + 64][lc] = pa1;
            *(uint4*)&smB[nb][lr][lc]      = pb0;
            *(uint4*)&smB[nb][lr + 64][lc] = pb1;
            __syncthreads();
        }
    }

    // epilogue
#pragma unroll
    for (int mi = 0; mi < 2; mi++) {
        const int r0g = row0 + wm * 32 + mi * 16 + g;
#pragma unroll
        for (int ni = 0; ni < 8; ni++) {
            const int c = col0 + wn * 64 + ni * 8 + t2;
            const float b0 = bias[c], b1 = bias[c + 1];
            float2 v0, v1;
            v0.x = acc[mi][ni][0] + b0;  v0.y = acc[mi][ni][1] + b1;
            v1.x = acc[mi][ni][2] + b0;  v1.y = acc[mi][ni][3] + b1;
            if (ep == 3) {
                *(uint32_t*)(obf + (size_t)r0g * Ndim + c)       = bf2u32(v0.x, v0.y);
                *(uint32_t*)(obf + (size_t)(r0g + 8) * Ndim + c) = bf2u32(v1.x, v1.y);
            } else if (ep == 1) {
                v0.x = gelu_exact(v0.x); v0.y = gelu_exact(v0.y);
                v1.x = gelu_exact(v1.x); v1.y = gelu_exact(v1.y);
                const int P = 3 * Ndim;
                uint32_t h0 = bf2u32(v0.x, v0.y);
                uint32_t h1 = bf2u32(v1.x, v1.y);
                __nv_bfloat162 hb0 = *(__nv_bfloat162*)&h0;
                __nv_bfloat162 hb1 = *(__nv_bfloat162*)&h1;
                uint32_t l0 = bf2u32(v0.x - __bfloat162float(hb0.x),
                                     v0.y - __bfloat162float(hb0.y));
                uint32_t l1 = bf2u32(v1.x - __bfloat162float(hb1.x),
                                     v1.y - __bfloat162float(hb1.y));
                __nv_bfloat16* d0 = obf + (size_t)r0g * P + c;
                __nv_bfloat16* d1 = obf + (size_t)(r0g + 8) * P + c;
                *(uint32_t*)(d0)            = h0;
                *(uint32_t*)(d0 + Ndim)     = l0;
                *(uint32_t*)(d0 + 2 * Ndim) = h0;
                *(uint32_t*)(d1)            = h1;
                *(uint32_t*)(d1 + Ndim)     = l1;
                *(uint32_t*)(d1 + 2 * Ndim) = h1;
            } else {
                float2 r0v = *(const float2*)(resid + (size_t)r0g * Ndim + c);
                float2 r1v = *(const float2*)(resid + (size_t)(r0g + 8) * Ndim + c);
                v0.x += r0v.x; v0.y += r0v.y;
                v1.x += r1v.x; v1.y += r1v.y;
                *(float2*)(outp + (size_t)r0g * Ndim + c)       = v0;
                *(float2*)(outp + (size_t)(r0g + 8) * Ndim + c) = v1;
            }
        }
    }
}

// ---------------------------------------------------------------------------
// V transpose: vb[token][256] bf16 -> vt[(b*256+d)][s] bf16
// ---------------------------------------------------------------------------
__global__ __launch_bounds__(256)
void vtrans_kernel(const __nv_bfloat16* __restrict__ vb,
                   __nv_bfloat16* __restrict__ vt)
{
    __shared__ __nv_bfloat16 S[64][264];
    const int b  = blockIdx.y;
    const int t0 = blockIdx.x * 64;
    const int tid = threadIdx.x;
#pragma unroll
    for (int i = 0; i < 8; i++) {
        int idx = i * 256 + tid;
        int r = idx >> 5, seg = idx & 31;
        *(uint4*)&S[r][seg * 8] =
            *(const uint4*)(vb + ((size_t)(b * Sc + t0 + r)) * Dc + seg * 8);
    }
    __syncthreads();
#pragma unroll
    for (int i = 0; i < 8; i++) {
        int idx = i * 256 + tid;
        int d = idx >> 3, seg = idx & 7;
        __nv_bfloat16 tmp[8];
#pragma unroll
        for (int j = 0; j < 8; j++) tmp[j] = S[seg * 8 + j][d];
        *(uint4*)(vt + ((size_t)(b * 256 + d)) * Sc + t0 + seg * 8) = *(uint4*)tmp;
    }
}

// ---------------------------------------------------------------------------
// Tensor-core flash attention, causal. grid (S/64, B*H), block 128 (4 warps).
// QK^T and PV via mma.m16n8k16 bf16; fp32 online softmax with fexp.
// Output: ctx as bf16x3 into a3c (pitch 768).
// ---------------------------------------------------------------------------
__global__ __launch_bounds__(128)
void attn_mma_kernel(const __nv_bfloat16* __restrict__ Qb,
                     const __nv_bfloat16* __restrict__ Kb,
                     const __nv_bfloat16* __restrict__ Vt,
                     __nv_bfloat16* __restrict__ a3c)
{
    __shared__ __align__(16) __nv_bfloat16 Ks[64][40];
    __shared__ __align__(16) __nv_bfloat16 Vs[32][72];

    const int qt  = blockIdx.x;
    const int bh  = blockIdx.y;
    const int b   = bh >> 3;
    const int hh  = bh & 7;
    const int tid = threadIdx.x;
    const int w   = tid >> 5;
    const int lane = tid & 31;
    const int g   = lane >> 2;
    const int t2  = (lane & 3) * 2;

    const int q0 = qt * 64;
    const int r0 = q0 + w * 16 + g;          // query row (c0,c1)
    const int r1 = r0 + 8;                   // query row (c2,c3)

    uint32_t aq[2][4];
    {
        const __nv_bfloat16* qp  = Qb + ((size_t)(b * Sc + r0)) * Dc + hh * DHc;
        const __nv_bfloat16* qp8 = qp + 8 * Dc;
#pragma unroll
        for (int ks = 0; ks < 2; ks++) {
            aq[ks][0] = *(const uint32_t*)(qp  + ks * 16 + t2);
            aq[ks][1] = *(const uint32_t*)(qp8 + ks * 16 + t2);
            aq[ks][2] = *(const uint32_t*)(qp  + ks * 16 + t2 + 8);
            aq[ks][3] = *(const uint32_t*)(qp8 + ks * 16 + t2 + 8);
        }
    }

    float octx[4][4];
#pragma unroll
    for (int i = 0; i < 4; i++)
#pragma unroll
        for (int j = 0; j < 4; j++) octx[i][j] = 0.f;
    float m0 = -1e30f, m1 = -1e30f, l0 = 0.f, l1 = 0.f;
    const float scale = 0.17677669529663689f;

    const int kmax = q0 + 64;
    for (int kt = 0; kt < kmax; kt += 64) {
        __syncthreads();
#pragma unroll
        for (int i = 0; i < 2; i++) {
            int idx = i * 128 + tid;
            int r = idx >> 2, seg = idx & 3;
            *(uint4*)&Ks[r][seg * 8] =
                *(const uint4*)(Kb + ((size_t)(b * Sc + kt + r)) * Dc + hh * DHc + seg * 8);
        }
#pragma unroll
        for (int i = 0; i < 2; i++) {
            int idx = i * 128 + tid;
            int r = idx >> 3, seg = idx & 7;
            *(uint4*)&Vs[r][seg * 8] =
                *(const uint4*)(Vt + ((size_t)(bh * DHc + r)) * Sc + kt + seg * 8);
        }
        __syncthreads();

        float sacc[8][4];
#pragma unroll
        for (int ni = 0; ni < 8; ni++)
#pragma unroll
            for (int c = 0; c < 4; c++) sacc[ni][c] = 0.f;

#pragma unroll
        for (int ks = 0; ks < 2; ks++) {
#pragma unroll
            for (int ni = 0; ni < 8; ni++) {
                uint32_t b0 = *(const uint32_t*)&Ks[ni * 8 + g][ks * 16 + t2];
                uint32_t b1 = *(const uint32_t*)&Ks[ni * 8 + g][ks * 16 + t2 + 8];
                asm volatile(
                    "mma.sync.aligned.m16n8k16.row.col.f32.bf16.bf16.f32 "
                    "{%0,%1,%2,%3}, {%4,%5,%6,%7}, {%8,%9}, {%0,%1,%2,%3};"
                    : "+f"(sacc[ni][0]), "+f"(sacc[ni][1]),
                      "+f"(sacc[ni][2]), "+f"(sacc[ni][3])
                    : "r"(aq[ks][0]), "r"(aq[ks][1]),
                      "r"(aq[ks][2]), "r"(aq[ks][3]),
                      "r"(b0), "r"(b1));
            }
        }

        // scale + causal mask (only diagonal tile)
#pragma unroll
        for (int ni = 0; ni < 8; ni++)
#pragma unroll
            for (int c = 0; c < 4; c++) sacc[ni][c] *= scale;
        if (kt == q0) {
#pragma unroll
            for (int ni = 0; ni < 8; ni++) {
                int c0g = kt + ni * 8 + t2;
                if (c0g     > r0) sacc[ni][0] = -1e30f;
                if (c0g + 1 > r0) sacc[ni][1] = -1e30f;
                if (c0g     > r1) sacc[ni][2] = -1e30f;
                if (c0g + 1 > r1) sacc[ni][3] = -1e30f;
            }
        }

        // row maxima
        float tm0 = -1e30f, tm1 = -1e30f;
#pragma unroll
        for (int ni = 0; ni < 8; ni++) {
            tm0 = fmaxf(tm0, fmaxf(sacc[ni][0], sacc[ni][1]));
            tm1 = fmaxf(tm1, fmaxf(sacc[ni][2], sacc[ni][3]));
        }
        tm0 = fmaxf(tm0, __shfl_xor_sync(0xffffffffu, tm0, 1));
        tm0 = fmaxf(tm0, __shfl_xor_sync(0xffffffffu, tm0, 2));
        tm1 = fmaxf(tm1, __shfl_xor_sync(0xffffffffu, tm1, 1));
        tm1 = fmaxf(tm1, __shfl_xor_sync(0xffffffffu, tm1, 2));

        float nm0 = fmaxf(m0, tm0), nm1 = fmaxf(m1, tm1);
        float corr0 = fexp(m0 - nm0), corr1 = fexp(m1 - nm1);
        m0 = nm0; m1 = nm1;
        l0 *= corr0; l1 *= corr1;
#pragma unroll
        for (int nd = 0; nd < 4; nd++) {
            octx[nd][0] *= corr0; octx[nd][1] *= corr0;
            octx[nd][2] *= corr1; octx[nd][3] *= corr1;
        }

        // exp, rowsum, pack P into A-fragments
        uint32_t pa[4][4];
        float rs0 = 0.f, rs1 = 0.f;
#pragma unroll
        for (int ni = 0; ni < 8; ni++) {
            float p0 = fexp(sacc[ni][0] - m0);
            float p1 = fexp(sacc[ni][1] - m0);
            float p2 = fexp(sacc[ni][2] - m1);
            float p3 = fexp(sacc[ni][3] - m1);
            rs0 += p0 + p1;
            rs1 += p2 + p3;
            const int ks2 = ni >> 1;
            if ((ni & 1) == 0) {
                pa[ks2][0] = bf2u32(p0, p1);
                pa[ks2][1] = bf2u32(p2, p3);
            } else {
                pa[ks2][2] = bf2u32(p0, p1);
                pa[ks2][3] = bf2u32(p2, p3);
            }
        }
        rs0 += __shfl_xor_sync(0xffffffffu, rs0, 1);
        rs0 += __shfl_xor_sync(0xffffffffu, rs0, 2);
        rs1 += __shfl_xor_sync(0xffffffffu, rs1, 1);
        rs1 += __shfl_xor_sync(0xffffffffu, rs1, 2);
        l0 += rs0; l1 += rs1;

        // PV
#pragma unroll
        for (int ks2 = 0; ks2 < 4; ks2++) {
#pragma unroll
            for (int nd = 0; nd < 4; nd++) {
                uint32_t b0 = *(const uint32_t*)&Vs[nd * 8 + g][ks2 * 16 + t2];
                uint32_t b1 = *(const uint32_t*)&Vs[nd * 8 + g][ks2 * 16 + t2 + 8];
                asm volatile(
                    "mma.sync.aligned.m16n8k16.row.col.f32.bf16.bf16.f32 "
                    "{%0,%1,%2,%3}, {%4,%5,%6,%7}, {%8,%9}, {%0,%1,%2,%3};"
                    : "+f"(octx[nd][0]), "+f"(octx[nd][1]),
                      "+f"(octx[nd][2]), "+f"(octx[nd][3])
                    : "r"(pa[ks2][0]), "r"(pa[ks2][1]),
                      "r"(pa[ks2][2]), "r"(pa[ks2][3]),
                      "r"(b0), "r"(b1));
            }
        }
    }

    // epilogue: ctx / l -> bf16x3 into a3c (pitch 768)
    const float inv0 = 1.f / l0, inv1 = 1.f / l1;
    const size_t tr0 = (size_t)(b * Sc + r0) * 768;
    const size_t tr1 = (size_t)(b * Sc + r1) * 768;
#pragma unroll
    for (int nd = 0; nd < 4; nd++) {
        const int col = hh * 32 + nd * 8 + t2;
        float x0 = octx[nd][0] * inv0, x1 = octx[nd][1] * inv0;
        float y0 = octx[nd][2] * inv1, y1 = octx[nd][3] * inv1;
        uint32_t h0 = bf2u32(x0, x1);
        uint32_t h1 = bf2u32(y0, y1);
        __nv_bfloat162 hb0 = *(__nv_bfloat162*)&h0;
        __nv_bfloat162 hb1 = *(__nv_bfloat162*)&h1;
        uint32_t lo0 = bf2u32(x0 - __bfloat162float(hb0.x), x1 - __bfloat162float(hb0.y));
        uint32_t lo1 = bf2u32(y0 - __bfloat162float(hb1.x), y1 - __bfloat162float(hb1.y));
        *(uint32_t*)(a3c + tr0 + col)       = h0;
        *(uint32_t*)(a3c + tr0 + 256 + col) = lo0;
        *(uint32_t*)(a3c + tr0 + 512 + col) = h0;
        *(uint32_t*)(a3c + tr1 + col)       = h1;
        *(uint32_t*)(a3c + tr1 + 256 + col) = lo1;
        *(uint32_t*)(a3c + tr1 + 512 + col) = h1;
    }
}

// ---------------------------------------------------------------------------
// Embedding + PE: fp32 h + bf16x3 a3
// ---------------------------------------------------------------------------
__global__ void embed_kernel(const int* __restrict__ x,
                             const float* __restrict__ emb,
                             const float* __restrict__ pe)
{
    int gid = blockIdx.x * 256 + threadIdx.x;
    int t = gid >> 8;
    int d = gid & 255;
    float v = emb[x[t] * Dc + d] + pe[(t & (Sc - 1)) * Dc + d];
    g_h[gid] = v;
    __nv_bfloat16 hi = __float2bfloat16(v);
    __nv_bfloat16 lo = __float2bfloat16(v - __bfloat162float(hi));
    size_t b3 = (size_t)t * 768 + d;
    g_a3[b3]       = hi;
    g_a3[b3 + 256] = lo;
    g_a3[b3 + 512] = hi;
}

// ---------------------------------------------------------------------------
// LayerNorm: fp32 Y + bf16x3 a3
// ---------------------------------------------------------------------------
__global__ __launch_bounds__(256)
void ln_kernel(const float* __restrict__ X,
               const float* __restrict__ gw,
               const float* __restrict__ bw,
               float* __restrict__ Y,
               __nv_bfloat16* __restrict__ a3)
{
    const int row = blockIdx.x;
    const int d   = threadIdx.x;
    __shared__ float red[8];
    __shared__ float bc;

    float v = X[(size_t)row * Dc + d];
    float s = v;
#pragma unroll
    for (int o = 16; o > 0; o >>= 1) s += __shfl_down_sync(0xffffffffu, s, o);
    if ((d & 31) == 0) red[d >> 5] = s;
    __syncthreads();
    if (d == 0) {
        float t = 0.f;
#pragma unroll
        for (int i = 0; i < 8; i++) t += red[i];
        bc = t * (1.0f / Dc);
    }
    __syncthreads();
    const float m  = bc;
    const float dv = v - m;

    float s2 = dv * dv;
#pragma unroll
    for (int o = 16; o > 0; o >>= 1) s2 += __shfl_down_sync(0xffffffffu, s2, o);
    __syncthreads();
    if ((d & 31) == 0) red[d >> 5] = s2;
    __syncthreads();
    if (d == 0) {
        float t = 0.f;
#pragma unroll
        for (int i = 0; i < 8; i++) t += red[i];
        bc = t * (1.0f / Dc);
    }
    __syncthreads();
    float y = gw[d] * dv * rsqrtf(bc + 1e-12f) + bw[d];
    Y[(size_t)row * Dc + d] = y;
    __nv_bfloat16 hi = __float2bfloat16(y);
    __nv_bfloat16 lo = __float2bfloat16(y - __bfloat162float(hi));
    size_t b3 = (size_t)row * 768 + d;
    a3[b3]       = hi;
    a3[b3 + 256] = lo;
    a3[b3 + 512] = hi;
}

// ---------------------------------------------------------------------------
// Output projection (M=4)
// ---------------------------------------------------------------------------
__global__ __launch_bounds__(256)
void outproj_kernel(const float* __restrict__ ow,
                    const float* __restrict__ ob,
                    float* __restrict__ out)
{
    const int w    = threadIdx.x >> 5;
    const int lane = threadIdx.x & 31;
    const int t    = blockIdx.x * 8 + w;
    const float* hr = g_h + (size_t)t * Dc;

    float hv[8];
#pragma unroll
    for (int i = 0; i < 8; i++) hv[i] = hr[lane + 32 * i];

#pragma unroll
    for (int m = 0; m < Mc; m++) {
        const float* wr = ow + m * Dc;
        float p = 0.f;
#pragma unroll
        for (int i = 0; i < 8; i++) p += hv[i] * wr[lane + 32 * i];
#pragma unroll
        for (int o = 16; o > 0; o >>= 1) p += __shfl_down_sync(0xffffffffu, p, o);
        if (lane == 0) out[t * Mc + m] = p + ob[m];
    }
}

// ---------------------------------------------------------------------------
// Host orchestration (graph-capturable)
// ---------------------------------------------------------------------------
extern "C" void kernel_launch(void* const* d_in, const int* in_sizes, int n_in,
                              void* d_out, int out_size)
{
    const int*   x     = (const int*)  d_in[0];
    const float* emb   = (const float*)d_in[1];
    const float* pe    = (const float*)d_in[2];
    const float* q_w   = (const float*)d_in[3];
    const float* q_b   = (const float*)d_in[4];
    const float* k_w   = (const float*)d_in[5];
    const float* k_b   = (const float*)d_in[6];
    const float* v_w   = (const float*)d_in[7];
    const float* v_b   = (const float*)d_in[8];
    const float* o_w   = (const float*)d_in[9];
    const float* o_b   = (const float*)d_in[10];
    const float* ln1_g = (const float*)d_in[11];
    const float* ln1_b = (const float*)d_in[12];
    const float* f1_w  = (const float*)d_in[13];
    const float* f1_b  = (const float*)d_in[14];
    const float* f2_w  = (const float*)d_in[15];
    const float* f2_b  = (const float*)d_in[16];
    const float* ln2_g = (const float*)d_in[17];
    const float* ln2_b = (const float*)d_in[18];
    const float* out_w = (const float*)d_in[19];
    const float* out_b = (const float*)d_in[20];
    float* out = (float*)d_out;

    float *h, *tmp, *ao;
    __nv_bfloat16 *qb, *kb, *vb, *vt, *a3, *a3c, *a3f, *w3;
    cudaGetSymbolAddress((void**)&h,   g_h);
    cudaGetSymbolAddress((void**)&tmp, g_tmp);
    cudaGetSymbolAddress((void**)&ao,  g_ao);
    cudaGetSymbolAddress((void**)&qb,  g_qb);
    cudaGetSymbolAddress((void**)&kb,  g_kb);
    cudaGetSymbolAddress((void**)&vb,  g_vb);
    cudaGetSymbolAddress((void**)&vt,  g_vt);
    cudaGetSymbolAddress((void**)&a3,  g_a3);
    cudaGetSymbolAddress((void**)&a3c, g_a3c);
    cudaGetSymbolAddress((void**)&a3f, g_a3f);
    cudaGetSymbolAddress((void**)&w3,  g_w3);

    // weight -> bf16x3: one launch per weight type, all layers
    convw_kernel<<<512,  256>>>(q_w,  w3,           Dc, Dc);
    convw_kernel<<<512,  256>>>(k_w,  w3 + 196608,  Dc, Dc);
    convw_kernel<<<512,  256>>>(v_w,  w3 + 393216,  Dc, Dc);
    convw_kernel<<<512,  256>>>(o_w,  w3 + 589824,  Dc, Dc);
    convw_kernel<<<2048, 256>>>(f1_w, w3 + 786432,  Dc, Ic);
    convw_kernel<<<2048, 256>>>(f2_w, w3 + 1572864, Ic, Dc);

    embed_kernel<<<TOK * Dc / 256, 256>>>(x, emb, pe);

    const dim3 gN2(2, 64);              // N=256 GEMMs
    const dim3 gN8(8, 64);              // N=1024 GEMM
    const dim3 gAttn(Sc / 64, Bc * Hc); // (16, 64)
    const dim3 gVT(Sc / 64, Bc);        // (16, 8)

    for (int l = 0; l < Lc; l++) {
        const __nv_bfloat16* wl = w3 + (size_t)l * LWS;
        const size_t bo = (size_t)l * Dc;

        gemm3_kernel<<<gN2, 256>>>(a3, wl,          q_b + bo, nullptr, nullptr, qb, Dc, 768, 3);
        gemm3_kernel<<<gN2, 256>>>(a3, wl + 196608, k_b + bo, nullptr, nullptr, kb, Dc, 768, 3);
        gemm3_kernel<<<gN2, 256>>>(a3, wl + 393216, v_b + bo, nullptr, nullptr, vb, Dc, 768, 3);

        vtrans_kernel<<<gVT, 256>>>(vb, vt);
        attn_mma_kernel<<<gAttn, 128>>>(qb, kb, vt, a3c);

        gemm3_kernel<<<gN2, 256>>>(a3c, wl + 589824, o_b + bo, h, tmp, nullptr, Dc, 768, 2);
        ln_kernel<<<TOK, 256>>>(tmp, ln1_g + bo, ln1_b + bo, ao, a3);

        gemm3_kernel<<<gN8, 256>>>(a3, wl + 786432, f1_b + (size_t)l * Ic,
                                   nullptr, nullptr, a3f, Ic, 768, 1);
        gemm3_kernel<<<gN2, 256>>>(a3f, wl + 1572864, f2_b + bo, ao, tmp, nullptr, Dc, 3072, 2);
        ln_kernel<<<TOK, 256>>>(tmp, ln2_g + bo, ln2_b + bo, h, a3);
    }

    outproj_kernel<<<TOK / 8, 256>>>(out_w, out_b, out);
}

// round 15
// speedup vs baseline: 2.8764x; 1.3081x over previous
#include <cuda_runtime.h>
#include <cuda_bf16.h>
#include <math.h>
#include <stdint.h>

#define Lc  4
#define Bc  8
#define Sc  1024
#define Dc  256
#define Hc  8
#define DHc 32
#define Ic  1024
#define Mc  4
#define TOK 8192
#define LWS 1507328ull   // per-layer stride in g_w3 (o:196608 + f1:786432 + f2:524288)

// ---------------------------------------------------------------------------
// Scratch (__device__ globals; no allocations allowed)
// ---------------------------------------------------------------------------
__device__ float g_h  [TOK*Dc];
__device__ float g_tmp[TOK*Dc];
__device__ float g_ao [TOK*Dc];
__device__ __nv_bfloat16 g_qkv[TOK*768];       // [q|k|v] pitch 768
__device__ __nv_bfloat16 g_a3 [TOK*3*Dc];      // [hi|lo|hi] pitch 768
__device__ __nv_bfloat16 g_a3c[TOK*3*Dc];      // ctx bf16x3 pitch 768
__device__ __nv_bfloat16 g_a3f[TOK*2*Ic];      // ff [hi|lo] pitch 2048
__device__ __nv_bfloat16 g_w3 [Lc*LWS];        // o(3t) | f1(3t) | f2(2t)
__device__ __nv_bfloat16 g_wq [Lc*768*256];    // merged qkv weights, 1-term
__device__ float         g_bq [Lc*768];        // merged qkv bias

__device__ __forceinline__ float gelu_exact(float v) {
    return 0.5f * v * (1.0f + erff(v * 0.70710678118654752f));
}

// Fast exp on FMA pipe (no MUFU)
__device__ __forceinline__ float fexp(float x) {
    float y = fmaxf(x * 1.4426950408889634f, -125.0f);
    float t = y + 12582912.0f;
    int   k = __float_as_int(t) - 0x4B400000;
    float f = y - (t - 12582912.0f);
    float p = 9.6181294e-3f;
    p = fmaf(p, f, 5.5504109e-2f);
    p = fmaf(p, f, 2.4022651e-1f);
    p = fmaf(p, f, 6.9314718e-1f);
    p = fmaf(p, f, 1.0f);
    return __int_as_float(__float_as_int(p) + (k << 23));
}

__device__ __forceinline__ uint32_t bf2u32(float a, float b) {
    __nv_bfloat162 t;
    t.x = __float2bfloat16(a);
    t.y = __float2bfloat16(b);
    return *(uint32_t*)&t;
}

// ---------------------------------------------------------------------------
// Weight conversions
// ---------------------------------------------------------------------------
__global__ __launch_bounds__(256)   // 3-term [hi|hi|lo], pitch 3K
void convw3_kernel(const float* __restrict__ src, __nv_bfloat16* __restrict__ dst,
                   int K, int Nper)
{
    int gid = blockIdx.x * 256 + threadIdx.x;
    int kh = K >> 1;
    int l  = gid / (Nper * kh);
    int rem = gid - l * (Nper * kh);
    int n  = rem / kh;
    int k  = (rem - n * kh) * 2;
    float2 v = *(const float2*)(src + ((size_t)l * Nper + n) * K + k);
    __nv_bfloat162 hh, ll;
    hh.x = __float2bfloat16(v.x); hh.y = __float2bfloat16(v.y);
    ll.x = __float2bfloat16(v.x - __bfloat162float(hh.x));
    ll.y = __float2bfloat16(v.y - __bfloat162float(hh.y));
    __nv_bfloat16* d = dst + (size_t)l * LWS + (size_t)n * 3 * K;
    *(__nv_bfloat162*)(d + k)         = hh;
    *(__nv_bfloat162*)(d + K + k)     = hh;
    *(__nv_bfloat162*)(d + 2 * K + k) = ll;
}

__global__ __launch_bounds__(256)   // 2-term [hi|hi], pitch 2K
void convw2_kernel(const float* __restrict__ src, __nv_bfloat16* __restrict__ dst,
                   int K, int Nper)
{
    int gid = blockIdx.x * 256 + threadIdx.x;
    int kh = K >> 1;
    int l  = gid / (Nper * kh);
    int rem = gid - l * (Nper * kh);
    int n  = rem / kh;
    int k  = (rem - n * kh) * 2;
    float2 v = *(const float2*)(src + ((size_t)l * Nper + n) * K + k);
    __nv_bfloat162 hh;
    hh.x = __float2bfloat16(v.x); hh.y = __float2bfloat16(v.y);
    __nv_bfloat16* d = dst + (size_t)l * LWS + (size_t)n * 2 * K;
    *(__nv_bfloat162*)(d + k)     = hh;
    *(__nv_bfloat162*)(d + K + k) = hh;
}

__global__ __launch_bounds__(256)   // merged qkv, 1-term bf16, pitch 256
void qkvw_kernel(const float* __restrict__ qw, const float* __restrict__ kw,
                 const float* __restrict__ vw, __nv_bfloat16* __restrict__ dst)
{
    int gid = blockIdx.x * 256 + threadIdx.x;   // Lc*768*128
    int l = gid / (768 * 128);
    int rem = gid - l * 768 * 128;
    int n = rem >> 7;
    int k = (rem & 127) * 2;
    const float* src = (n < 256) ? qw + ((size_t)l * 256 + n) * 256
                     : (n < 512) ? kw + ((size_t)l * 256 + n - 256) * 256
                                 : vw + ((size_t)l * 256 + n - 512) * 256;
    float2 v = *(const float2*)(src + k);
    __nv_bfloat162 hh;
    hh.x = __float2bfloat16(v.x); hh.y = __float2bfloat16(v.y);
    *(__nv_bfloat162*)(dst + ((size_t)l * 768 + n) * 256 + k) = hh;
}

__global__ void bqkv_kernel(const float* __restrict__ qb, const float* __restrict__ kb,
                            const float* __restrict__ vb, float* __restrict__ dst)
{
    int gid = blockIdx.x * 256 + threadIdx.x;   // Lc*768
    int l = gid / 768, n = gid - l * 768;
    float v = (n < 256) ? qb[l * 256 + n]
            : (n < 512) ? kb[l * 256 + n - 256]
                        : vb[l * 256 + n - 512];
    dst[gid] = v;
}

// ---------------------------------------------------------------------------
// HMMA GEMM: out[8192,N] = A[8192,K3]@W[N,K3]^T + bias, row pitches pA/pW
//   ep=1: gelu -> [hi|lo] bf16 (obf, pitch 2*Ndim)
//   ep=2: +resid -> fp32 (outp)
//   ep=3: -> bf16 (obf, pitch Ndim)
// ---------------------------------------------------------------------------
#define SPAD 40

__global__ __launch_bounds__(256)
void gemm3_kernel(const __nv_bfloat16* __restrict__ A3, int pA,
                  const __nv_bfloat16* __restrict__ W3, int pW,
                  const float* __restrict__ bias,
                  const float* __restrict__ resid,
                  float* __restrict__ outp,
                  __nv_bfloat16* __restrict__ obf,
                  int Ndim, int K3, int ep)
{
    __shared__ __align__(16) __nv_bfloat16 smA[2][128][SPAD];
    __shared__ __align__(16) __nv_bfloat16 smB[2][128][SPAD];

    const int tid  = threadIdx.x;
    const int wid  = tid >> 5;
    const int lane = tid & 31;
    const int g    = lane >> 2;
    const int t2   = (lane & 3) * 2;
    const int wm   = wid >> 1;
    const int wn   = wid & 1;

    const int row0 = blockIdx.y * 128;
    const int col0 = blockIdx.x * 128;

    const int lr = tid >> 2;
    const int lc = (tid & 3) * 8;
    const __nv_bfloat16* gA0 = A3 + (size_t)(row0 + lr)      * pA + lc;
    const __nv_bfloat16* gA1 = A3 + (size_t)(row0 + lr + 64) * pA + lc;
    const __nv_bfloat16* gB0 = W3 + (size_t)(col0 + lr)      * pW + lc;
    const __nv_bfloat16* gB1 = W3 + (size_t)(col0 + lr + 64) * pW + lc;

    float acc[2][8][4];
#pragma unroll
    for (int i = 0; i < 2; i++)
#pragma unroll
        for (int j = 0; j < 8; j++)
#pragma unroll
            for (int c = 0; c < 4; c++) acc[i][j][c] = 0.f;

    const int nc = K3 >> 5;

    {
        *(uint4*)&smA[0][lr][lc]      = *(const uint4*)gA0;
        *(uint4*)&smA[0][lr + 64][lc] = *(const uint4*)gA1;
        *(uint4*)&smB[0][lr][lc]      = *(const uint4*)gB0;
        *(uint4*)&smB[0][lr + 64][lc] = *(const uint4*)gB1;
    }
    __syncthreads();

    for (int i = 0; i < nc; i++) {
        const int buf = i & 1;
        uint4 pa0, pa1, pb0, pb1;
        const bool more = (i + 1 < nc);
        if (more) {
            const int ko = (i + 1) * 32;
            pa0 = *(const uint4*)(gA0 + ko);
            pa1 = *(const uint4*)(gA1 + ko);
            pb0 = *(const uint4*)(gB0 + ko);
            pb1 = *(const uint4*)(gB1 + ko);
        }

#pragma unroll
        for (int kk = 0; kk < 32; kk += 16) {
            uint32_t af[2][4];
#pragma unroll
            for (int mi = 0; mi < 2; mi++) {
                const __nv_bfloat16* ap = &smA[buf][wm * 32 + mi * 16 + g][kk + t2];
                af[mi][0] = *(const uint32_t*)(ap);
                af[mi][1] = *(const uint32_t*)(ap + 8 * SPAD);
                af[mi][2] = *(const uint32_t*)(ap + 8);
                af[mi][3] = *(const uint32_t*)(ap + 8 * SPAD + 8);
            }
#pragma unroll
            for (int ni = 0; ni < 8; ni++) {
                const __nv_bfloat16* bp = &smB[buf][wn * 64 + ni * 8 + g][kk + t2];
                uint32_t b0 = *(const uint32_t*)(bp);
                uint32_t b1 = *(const uint32_t*)(bp + 8);
#pragma unroll
                for (int mi = 0; mi < 2; mi++) {
                    asm volatile(
                        "mma.sync.aligned.m16n8k16.row.col.f32.bf16.bf16.f32 "
                        "{%0,%1,%2,%3}, {%4,%5,%6,%7}, {%8,%9}, {%0,%1,%2,%3};"
                        : "+f"(acc[mi][ni][0]), "+f"(acc[mi][ni][1]),
                          "+f"(acc[mi][ni][2]), "+f"(acc[mi][ni][3])
                        : "r"(af[mi][0]), "r"(af[mi][1]),
                          "r"(af[mi][2]), "r"(af[mi][3]),
                          "r"(b0), "r"(b1));
                }
            }
        }

        if (more) {
            __syncthreads();
            const int nb = buf ^ 1;
            *(uint4*)&smA[nb][lr][lc]      = pa0;
            *(uint4*)&smA[nb][lr + 64][lc] = pa1;
            *(uint4*)&smB[nb][lr][lc]      = pb0;
            *(uint4*)&smB[nb][lr + 64][lc] = pb1;
            __syncthreads();
        }
    }

    // epilogue
#pragma unroll
    for (int mi = 0; mi < 2; mi++) {
        const int r0g = row0 + wm * 32 + mi * 16 + g;
#pragma unroll
        for (int ni = 0; ni < 8; ni++) {
            const int c = col0 + wn * 64 + ni * 8 + t2;
            const float b0 = bias[c], b1 = bias[c + 1];
            float2 v0, v1;
            v0.x = acc[mi][ni][0] + b0;  v0.y = acc[mi][ni][1] + b1;
            v1.x = acc[mi][ni][2] + b0;  v1.y = acc[mi][ni][3] + b1;
            if (ep == 3) {
                *(uint32_t*)(obf + (size_t)r0g * Ndim + c)       = bf2u32(v0.x, v0.y);
                *(uint32_t*)(obf + (size_t)(r0g + 8) * Ndim + c) = bf2u32(v1.x, v1.y);
            } else if (ep == 1) {
                v0.x = gelu_exact(v0.x); v0.y = gelu_exact(v0.y);
                v1.x = gelu_exact(v1.x); v1.y = gelu_exact(v1.y);
                const int P = 2 * Ndim;
                uint32_t h0 = bf2u32(v0.x, v0.y);
                uint32_t h1 = bf2u32(v1.x, v1.y);
                __nv_bfloat162 hb0 = *(__nv_bfloat162*)&h0;
                __nv_bfloat162 hb1 = *(__nv_bfloat162*)&h1;
                uint32_t l0 = bf2u32(v0.x - __bfloat162float(hb0.x),
                                     v0.y - __bfloat162float(hb0.y));
                uint32_t l1 = bf2u32(v1.x - __bfloat162float(hb1.x),
                                     v1.y - __bfloat162float(hb1.y));
                __nv_bfloat16* d0 = obf + (size_t)r0g * P + c;
                __nv_bfloat16* d1 = obf + (size_t)(r0g + 8) * P + c;
                *(uint32_t*)(d0)        = h0;
                *(uint32_t*)(d0 + Ndim) = l0;
                *(uint32_t*)(d1)        = h1;
                *(uint32_t*)(d1 + Ndim) = l1;
            } else {
                float2 r0v = *(const float2*)(resid + (size_t)r0g * Ndim + c);
                float2 r1v = *(const float2*)(resid + (size_t)(r0g + 8) * Ndim + c);
                v0.x += r0v.x; v0.y += r0v.y;
                v1.x += r1v.x; v1.y += r1v.y;
                *(float2*)(outp + (size_t)r0g * Ndim + c)       = v0;
                *(float2*)(outp + (size_t)(r0g + 8) * Ndim + c) = v1;
            }
        }
    }
}

// ---------------------------------------------------------------------------
// Tensor-core flash attention, causal. grid (S/64, B*H), block 128 (4 warps).
// Reads merged QKV (pitch 768: q@0, k@256, v@512); V transposed in-kernel.
// Output: ctx as bf16x3 into a3c (pitch 768).
// ---------------------------------------------------------------------------
__global__ __launch_bounds__(128)
void attn_mma_kernel(const __nv_bfloat16* __restrict__ QKV,
                     __nv_bfloat16* __restrict__ a3c)
{
    __shared__ __align__(16) __nv_bfloat16 Ks[64][40];
    __shared__ __align__(16) __nv_bfloat16 Vs[32][72];

    const int qt  = blockIdx.x;
    const int bh  = blockIdx.y;
    const int b   = bh >> 3;
    const int hh  = bh & 7;
    const int tid = threadIdx.x;
    const int w   = tid >> 5;
    const int lane = tid & 31;
    const int g   = lane >> 2;
    const int t2  = (lane & 3) * 2;

    const int q0 = qt * 64;
    const int r0 = q0 + w * 16 + g;
    const int r1 = r0 + 8;

    uint32_t aq[2][4];
    {
        const __nv_bfloat16* qp  = QKV + ((size_t)(b * Sc + r0)) * 768 + hh * DHc;
        const __nv_bfloat16* qp8 = qp + 8 * 768;
#pragma unroll
        for (int ks = 0; ks < 2; ks++) {
            aq[ks][0] = *(const uint32_t*)(qp  + ks * 16 + t2);
            aq[ks][1] = *(const uint32_t*)(qp8 + ks * 16 + t2);
            aq[ks][2] = *(const uint32_t*)(qp  + ks * 16 + t2 + 8);
            aq[ks][3] = *(const uint32_t*)(qp8 + ks * 16 + t2 + 8);
        }
    }

    float octx[4][4];
#pragma unroll
    for (int i = 0; i < 4; i++)
#pragma unroll
        for (int j = 0; j < 4; j++) octx[i][j] = 0.f;
    float m0 = -1e30f, m1 = -1e30f, l0 = 0.f, l1 = 0.f;
    const float scale = 0.17677669529663689f;

    const int kmax = q0 + 64;
    for (int kt = 0; kt < kmax; kt += 64) {
        __syncthreads();
        // K tile: 64 keys x 32 dh
#pragma unroll
        for (int i = 0; i < 2; i++) {
            int idx = i * 128 + tid;
            int r = idx >> 2, seg = idx & 3;
            *(uint4*)&Ks[r][seg * 8] =
                *(const uint4*)(QKV + ((size_t)(b * Sc + kt + r)) * 768 + 256 + hh * DHc + seg * 8);
        }
        // V tile transposed in-kernel: 64 tokens x 32 dh -> Vs[dh][token]
        {
            int token = tid >> 1;
            int dh0 = (tid & 1) * 16;
            const __nv_bfloat16* vp =
                QKV + ((size_t)(b * Sc + kt + token)) * 768 + 512 + hh * DHc + dh0;
            uint4 v0 = *(const uint4*)vp;
            uint4 v1 = *(const uint4*)(vp + 8);
            __nv_bfloat16 tmpv[16];
            *(uint4*)&tmpv[0] = v0;
            *(uint4*)&tmpv[8] = v1;
#pragma unroll
            for (int j = 0; j < 16; j++) Vs[dh0 + j][token] = tmpv[j];
        }
        __syncthreads();

        float sacc[8][4];
#pragma unroll
        for (int ni = 0; ni < 8; ni++)
#pragma unroll
            for (int c = 0; c < 4; c++) sacc[ni][c] = 0.f;

#pragma unroll
        for (int ks = 0; ks < 2; ks++) {
#pragma unroll
            for (int ni = 0; ni < 8; ni++) {
                uint32_t b0 = *(const uint32_t*)&Ks[ni * 8 + g][ks * 16 + t2];
                uint32_t b1 = *(const uint32_t*)&Ks[ni * 8 + g][ks * 16 + t2 + 8];
                asm volatile(
                    "mma.sync.aligned.m16n8k16.row.col.f32.bf16.bf16.f32 "
                    "{%0,%1,%2,%3}, {%4,%5,%6,%7}, {%8,%9}, {%0,%1,%2,%3};"
                    : "+f"(sacc[ni][0]), "+f"(sacc[ni][1]),
                      "+f"(sacc[ni][2]), "+f"(sacc[ni][3])
                    : "r"(aq[ks][0]), "r"(aq[ks][1]),
                      "r"(aq[ks][2]), "r"(aq[ks][3]),
                      "r"(b0), "r"(b1));
            }
        }

#pragma unroll
        for (int ni = 0; ni < 8; ni++)
#pragma unroll
            for (int c = 0; c < 4; c++) sacc[ni][c] *= scale;
        if (kt == q0) {
#pragma unroll
            for (int ni = 0; ni < 8; ni++) {
                int c0g = kt + ni * 8 + t2;
                if (c0g     > r0) sacc[ni][0] = -1e30f;
                if (c0g + 1 > r0) sacc[ni][1] = -1e30f;
                if (c0g     > r1) sacc[ni][2] = -1e30f;
                if (c0g + 1 > r1) sacc[ni][3] = -1e30f;
            }
        }

        float tm0 = -1e30f, tm1 = -1e30f;
#pragma unroll
        for (int ni = 0; ni < 8; ni++) {
            tm0 = fmaxf(tm0, fmaxf(sacc[ni][0], sacc[ni][1]));
            tm1 = fmaxf(tm1, fmaxf(sacc[ni][2], sacc[ni][3]));
        }
        tm0 = fmaxf(tm0, __shfl_xor_sync(0xffffffffu, tm0, 1));
        tm0 = fmaxf(tm0, __shfl_xor_sync(0xffffffffu, tm0, 2));
        tm1 = fmaxf(tm1, __shfl_xor_sync(0xffffffffu, tm1, 1));
        tm1 = fmaxf(tm1, __shfl_xor_sync(0xffffffffu, tm1, 2));

        float nm0 = fmaxf(m0, tm0), nm1 = fmaxf(m1, tm1);
        float corr0 = fexp(m0 - nm0), corr1 = fexp(m1 - nm1);
        m0 = nm0; m1 = nm1;
        l0 *= corr0; l1 *= corr1;
#pragma unroll
        for (int nd = 0; nd < 4; nd++) {
            octx[nd][0] *= corr0; octx[nd][1] *= corr0;
            octx[nd][2] *= corr1; octx[nd][3] *= corr1;
        }

        uint32_t pa[4][4];
        float rs0 = 0.f, rs1 = 0.f;
#pragma unroll
        for (int ni = 0; ni < 8; ni++) {
            float p0 = fexp(sacc[ni][0] - m0);
            float p1 = fexp(sacc[ni][1] - m0);
            float p2 = fexp(sacc[ni][2] - m1);
            float p3 = fexp(sacc[ni][3] - m1);
            rs0 += p0 + p1;
            rs1 += p2 + p3;
            const int ks2 = ni >> 1;
            if ((ni & 1) == 0) {
                pa[ks2][0] = bf2u32(p0, p1);
                pa[ks2][1] = bf2u32(p2, p3);
            } else {
                pa[ks2][2] = bf2u32(p0, p1);
                pa[ks2][3] = bf2u32(p2, p3);
            }
        }
        rs0 += __shfl_xor_sync(0xffffffffu, rs0, 1);
        rs0 += __shfl_xor_sync(0xffffffffu, rs0, 2);
        rs1 += __shfl_xor_sync(0xffffffffu, rs1, 1);
        rs1 += __shfl_xor_sync(0xffffffffu, rs1, 2);
        l0 += rs0; l1 += rs1;

#pragma unroll
        for (int ks2 = 0; ks2 < 4; ks2++) {
#pragma unroll
            for (int nd = 0; nd < 4; nd++) {
                uint32_t b0 = *(const uint32_t*)&Vs[nd * 8 + g][ks2 * 16 + t2];
                uint32_t b1 = *(const uint32_t*)&Vs[nd * 8 + g][ks2 * 16 + t2 + 8];
                asm volatile(
                    "mma.sync.aligned.m16n8k16.row.col.f32.bf16.bf16.f32 "
                    "{%0,%1,%2,%3}, {%4,%5,%6,%7}, {%8,%9}, {%0,%1,%2,%3};"
                    : "+f"(octx[nd][0]), "+f"(octx[nd][1]),
                      "+f"(octx[nd][2]), "+f"(octx[nd][3])
                    : "r"(pa[ks2][0]), "r"(pa[ks2][1]),
                      "r"(pa[ks2][2]), "r"(pa[ks2][3]),
                      "r"(b0), "r"(b1));
            }
        }
    }

    const float inv0 = 1.f / l0, inv1 = 1.f / l1;
    const size_t tr0 = (size_t)(b * Sc + r0) * 768;
    const size_t tr1 = (size_t)(b * Sc + r1) * 768;
#pragma unroll
    for (int nd = 0; nd < 4; nd++) {
        const int col = hh * 32 + nd * 8 + t2;
        float x0 = octx[nd][0] * inv0, x1 = octx[nd][1] * inv0;
        float y0 = octx[nd][2] * inv1, y1 = octx[nd][3] * inv1;
        uint32_t h0 = bf2u32(x0, x1);
        uint32_t h1 = bf2u32(y0, y1);
        __nv_bfloat162 hb0 = *(__nv_bfloat162*)&h0;
        __nv_bfloat162 hb1 = *(__nv_bfloat162*)&h1;
        uint32_t lo0 = bf2u32(x0 - __bfloat162float(hb0.x), x1 - __bfloat162float(hb0.y));
        uint32_t lo1 = bf2u32(y0 - __bfloat162float(hb1.x), y1 - __bfloat162float(hb1.y));
        *(uint32_t*)(a3c + tr0 + col)       = h0;
        *(uint32_t*)(a3c + tr0 + 256 + col) = lo0;
        *(uint32_t*)(a3c + tr0 + 512 + col) = h0;
        *(uint32_t*)(a3c + tr1 + col)       = h1;
        *(uint32_t*)(a3c + tr1 + 256 + col) = lo1;
        *(uint32_t*)(a3c + tr1 + 512 + col) = h1;
    }
}

// ---------------------------------------------------------------------------
// Embedding + PE: fp32 h + bf16x3 a3
// ---------------------------------------------------------------------------
__global__ void embed_kernel(const int* __restrict__ x,
                             const float* __restrict__ emb,
                             const float* __restrict__ pe)
{
    int gid = blockIdx.x * 256 + threadIdx.x;
    int t = gid >> 8;
    int d = gid & 255;
    float v = emb[x[t] * Dc + d] + pe[(t & (Sc - 1)) * Dc + d];
    g_h[gid] = v;
    __nv_bfloat16 hi = __float2bfloat16(v);
    __nv_bfloat16 lo = __float2bfloat16(v - __bfloat162float(hi));
    size_t b3 = (size_t)t * 768 + d;
    g_a3[b3]       = hi;
    g_a3[b3 + 256] = lo;
    g_a3[b3 + 512] = hi;
}

// ---------------------------------------------------------------------------
// LayerNorm: warp per row (8 floats/lane), fp32 Y + bf16x3 a3
// ---------------------------------------------------------------------------
__global__ __launch_bounds__(256)
void ln_kernel(const float* __restrict__ X,
               const float* __restrict__ gw,
               const float* __restrict__ bw,
               float* __restrict__ Y,
               __nv_bfloat16* __restrict__ a3)
{
    const int w    = threadIdx.x >> 5;
    const int lane = threadIdx.x & 31;
    const int row  = blockIdx.x * 8 + w;
    const int d    = lane * 8;
    const float* xr = X + (size_t)row * Dc + d;

    float v[8];
    *(float4*)&v[0] = *(const float4*)(xr);
    *(float4*)&v[4] = *(const float4*)(xr + 4);

    float s = v[0] + v[1] + v[2] + v[3] + v[4] + v[5] + v[6] + v[7];
#pragma unroll
    for (int o = 16; o > 0; o >>= 1) s += __shfl_xor_sync(0xffffffffu, s, o);
    const float m = s * (1.0f / Dc);

    float s2 = 0.f;
    float dv[8];
#pragma unroll
    for (int j = 0; j < 8; j++) { dv[j] = v[j] - m; s2 += dv[j] * dv[j]; }
#pragma unroll
    for (int o = 16; o > 0; o >>= 1) s2 += __shfl_xor_sync(0xffffffffu, s2, o);
    const float rstd = rsqrtf(s2 * (1.0f / Dc) + 1e-12f);

    float y[8];
    const float* gwp = gw + d;
    const float* bwp = bw + d;
#pragma unroll
    for (int j = 0; j < 8; j++) y[j] = gwp[j] * dv[j] * rstd + bwp[j];

    float* yr = Y + (size_t)row * Dc + d;
    *(float4*)(yr)     = *(float4*)&y[0];
    *(float4*)(yr + 4) = *(float4*)&y[4];

    __nv_bfloat16 hi[8], lo[8];
#pragma unroll
    for (int j = 0; j < 8; j++) {
        hi[j] = __float2bfloat16(y[j]);
        lo[j] = __float2bfloat16(y[j] - __bfloat162float(hi[j]));
    }
    __nv_bfloat16* a = a3 + (size_t)row * 768 + d;
    *(uint4*)(a)       = *(uint4*)hi;
    *(uint4*)(a + 256) = *(uint4*)lo;
    *(uint4*)(a + 512) = *(uint4*)hi;
}

// ---------------------------------------------------------------------------
// Output projection (M=4)
// ---------------------------------------------------------------------------
__global__ __launch_bounds__(256)
void outproj_kernel(const float* __restrict__ ow,
                    const float* __restrict__ ob,
                    float* __restrict__ out)
{
    const int w    = threadIdx.x >> 5;
    const int lane = threadIdx.x & 31;
    const int t    = blockIdx.x * 8 + w;
    const float* hr = g_h + (size_t)t * Dc;

    float hv[8];
#pragma unroll
    for (int i = 0; i < 8; i++) hv[i] = hr[lane + 32 * i];

#pragma unroll
    for (int m = 0; m < Mc; m++) {
        const float* wr = ow + m * Dc;
        float p = 0.f;
#pragma unroll
        for (int i = 0; i < 8; i++) p += hv[i] * wr[lane + 32 * i];
#pragma unroll
        for (int o = 16; o > 0; o >>= 1) p += __shfl_down_sync(0xffffffffu, p, o);
        if (lane == 0) out[t * Mc + m] = p + ob[m];
    }
}

// ---------------------------------------------------------------------------
// Host orchestration (graph-capturable)
// ---------------------------------------------------------------------------
extern "C" void kernel_launch(void* const* d_in, const int* in_sizes, int n_in,
                              void* d_out, int out_size)
{
    const int*   x     = (const int*)  d_in[0];
    const float* emb   = (const float*)d_in[1];
    const float* pe    = (const float*)d_in[2];
    const float* q_w   = (const float*)d_in[3];
    const float* q_b   = (const float*)d_in[4];
    const float* k_w   = (const float*)d_in[5];
    const float* k_b   = (const float*)d_in[6];
    const float* v_w   = (const float*)d_in[7];
    const float* v_b   = (const float*)d_in[8];
    const float* o_w   = (const float*)d_in[9];
    const float* o_b   = (const float*)d_in[10];
    const float* ln1_g = (const float*)d_in[11];
    const float* ln1_b = (const float*)d_in[12];
    const float* f1_w  = (const float*)d_in[13];
    const float* f1_b  = (const float*)d_in[14];
    const float* f2_w  = (const float*)d_in[15];
    const float* f2_b  = (const float*)d_in[16];
    const float* ln2_g = (const float*)d_in[17];
    const float* ln2_b = (const float*)d_in[18];
    const float* out_w = (const float*)d_in[19];
    const float* out_b = (const float*)d_in[20];
    float* out = (float*)d_out;

    float *h, *tmp, *ao, *bq;
    __nv_bfloat16 *qkv, *a3, *a3c, *a3f, *w3, *wq;
    cudaGetSymbolAddress((void**)&h,   g_h);
    cudaGetSymbolAddress((void**)&tmp, g_tmp);
    cudaGetSymbolAddress((void**)&ao,  g_ao);
    cudaGetSymbolAddress((void**)&qkv, g_qkv);
    cudaGetSymbolAddress((void**)&a3,  g_a3);
    cudaGetSymbolAddress((void**)&a3c, g_a3c);
    cudaGetSymbolAddress((void**)&a3f, g_a3f);
    cudaGetSymbolAddress((void**)&w3,  g_w3);
    cudaGetSymbolAddress((void**)&wq,  g_wq);
    cudaGetSymbolAddress((void**)&bq,  g_bq);

    // weight conversions
    qkvw_kernel<<<1536, 256>>>(q_w, k_w, v_w, wq);
    bqkv_kernel<<<12, 256>>>(q_b, k_b, v_b, bq);
    convw3_kernel<<<512,  256>>>(o_w,  w3,          Dc, Dc);  // o: 3-term
    convw3_kernel<<<2048, 256>>>(f1_w, w3 + 196608, Dc, Ic);  // f1: 3-term
    convw2_kernel<<<2048, 256>>>(f2_w, w3 + 983040, Ic, Dc);  // f2: 2-term

    embed_kernel<<<TOK * Dc / 256, 256>>>(x, emb, pe);

    const dim3 gQKV(6, 64);             // N=768
    const dim3 gN2(2, 64);              // N=256
    const dim3 gN8(8, 64);              // N=1024
    const dim3 gAttn(Sc / 64, Bc * Hc); // (16, 64)

    for (int l = 0; l < Lc; l++) {
        const __nv_bfloat16* wl = w3 + (size_t)l * LWS;
        const size_t bo = (size_t)l * Dc;

        // merged QKV: 1-term bf16, K=256 (hi slice of a3)
        gemm3_kernel<<<gQKV, 256>>>(a3, 768, wq + (size_t)l * 196608, 256,
                                    bq + (size_t)l * 768, nullptr, nullptr, qkv,
                                    768, 256, 3);

        attn_mma_kernel<<<gAttn, 128>>>(qkv, a3c);

        // o-proj: 3-term
        gemm3_kernel<<<gN2, 256>>>(a3c, 768, wl, 768, o_b + bo, h, tmp, nullptr,
                                   Dc, 768, 2);
        ln_kernel<<<TOK / 8, 256>>>(tmp, ln1_g + bo, ln1_b + bo, ao, a3);

        // f1: 3-term in, gelu, 2-term out
        gemm3_kernel<<<gN8, 256>>>(a3, 768, wl + 196608, 768,
                                   f1_b + (size_t)l * Ic, nullptr, nullptr, a3f,
                                   Ic, 768, 1);
        // f2: 2-term (ff [hi|lo] x W2 [hi|hi])
        gemm3_kernel<<<gN2, 256>>>(a3f, 2048, wl + 983040, 2048, f2_b + bo,
                                   ao, tmp, nullptr, Dc, 2048, 2);
        ln_kernel<<<TOK / 8, 256>>>(tmp, ln2_g + bo, ln2_b + bo, h, a3);
    }

    outproj_kernel<<<TOK / 8, 256>>>(out_w, out_b, out);
}

// round 16
// speedup vs baseline: 3.3338x; 1.1590x over previous
#include <cuda_runtime.h>
#include <cuda_bf16.h>
#include <math.h>
#include <stdint.h>

#define Lc  4
#define Bc  8
#define Sc  1024
#define Dc  256
#define Hc  8
#define DHc 32
#define Ic  1024
#define Mc  4
#define TOK 8192
#define LWS 1507328ull   // per-layer stride in g_w3 (o:196608 + f1:786432 + f2:524288)

// ---------------------------------------------------------------------------
// Scratch (__device__ globals; no allocations allowed)
// ---------------------------------------------------------------------------
__device__ float g_h  [TOK*Dc];
__device__ float g_tmp[TOK*Dc];
__device__ float g_ao [TOK*Dc];
__device__ __nv_bfloat16 g_qkv[TOK*768];       // [q|k|v] pitch 768
__device__ __nv_bfloat16 g_a3 [TOK*3*Dc];      // [hi|lo|hi] pitch 768
__device__ __nv_bfloat16 g_a3c[TOK*3*Dc];      // ctx bf16x3 pitch 768
__device__ __nv_bfloat16 g_a3f[TOK*2*Ic];      // ff [hi|lo] pitch 2048
__device__ __nv_bfloat16 g_w3 [Lc*LWS];        // o(3t) | f1(3t) | f2(2t)
__device__ __nv_bfloat16 g_wq [Lc*768*256];    // merged qkv weights, 1-term
__device__ float         g_bq [Lc*768];        // merged qkv bias

__device__ __forceinline__ float gelu_exact(float v) {
    return 0.5f * v * (1.0f + erff(v * 0.70710678118654752f));
}

// Fast exp on FMA pipe (no MUFU)
__device__ __forceinline__ float fexp(float x) {
    float y = fmaxf(x * 1.4426950408889634f, -125.0f);
    float t = y + 12582912.0f;
    int   k = __float_as_int(t) - 0x4B400000;
    float f = y - (t - 12582912.0f);
    float p = 9.6181294e-3f;
    p = fmaf(p, f, 5.5504109e-2f);
    p = fmaf(p, f, 2.4022651e-1f);
    p = fmaf(p, f, 6.9314718e-1f);
    p = fmaf(p, f, 1.0f);
    return __int_as_float(__float_as_int(p) + (k << 23));
}

__device__ __forceinline__ uint32_t bf2u32(float a, float b) {
    __nv_bfloat162 t;
    t.x = __float2bfloat16(a);
    t.y = __float2bfloat16(b);
    return *(uint32_t*)&t;
}

__device__ __forceinline__ uint32_t smem_u32(const void* p) {
    uint32_t a;
    asm("{ .reg .u64 t; cvta.to.shared.u64 t, %1; cvt.u32.u64 %0, t; }"
        : "=r"(a) : "l"(p));
    return a;
}

// ---------------------------------------------------------------------------
// Weight conversions
// ---------------------------------------------------------------------------
__global__ __launch_bounds__(256)   // 3-term [hi|hi|lo], pitch 3K
void convw3_kernel(const float* __restrict__ src, __nv_bfloat16* __restrict__ dst,
                   int K, int Nper)
{
    int gid = blockIdx.x * 256 + threadIdx.x;
    int kh = K >> 1;
    int l  = gid / (Nper * kh);
    int rem = gid - l * (Nper * kh);
    int n  = rem / kh;
    int k  = (rem - n * kh) * 2;
    float2 v = *(const float2*)(src + ((size_t)l * Nper + n) * K + k);
    __nv_bfloat162 hh, ll;
    hh.x = __float2bfloat16(v.x); hh.y = __float2bfloat16(v.y);
    ll.x = __float2bfloat16(v.x - __bfloat162float(hh.x));
    ll.y = __float2bfloat16(v.y - __bfloat162float(hh.y));
    __nv_bfloat16* d = dst + (size_t)l * LWS + (size_t)n * 3 * K;
    *(__nv_bfloat162*)(d + k)         = hh;
    *(__nv_bfloat162*)(d + K + k)     = hh;
    *(__nv_bfloat162*)(d + 2 * K + k) = ll;
}

__global__ __launch_bounds__(256)   // 2-term [hi|hi], pitch 2K
void convw2_kernel(const float* __restrict__ src, __nv_bfloat16* __restrict__ dst,
                   int K, int Nper)
{
    int gid = blockIdx.x * 256 + threadIdx.x;
    int kh = K >> 1;
    int l  = gid / (Nper * kh);
    int rem = gid - l * (Nper * kh);
    int n  = rem / kh;
    int k  = (rem - n * kh) * 2;
    float2 v = *(const float2*)(src + ((size_t)l * Nper + n) * K + k);
    __nv_bfloat162 hh;
    hh.x = __float2bfloat16(v.x); hh.y = __float2bfloat16(v.y);
    __nv_bfloat16* d = dst + (size_t)l * LWS + (size_t)n * 2 * K;
    *(__nv_bfloat162*)(d + k)     = hh;
    *(__nv_bfloat162*)(d + K + k) = hh;
}

__global__ __launch_bounds__(256)   // merged qkv, 1-term bf16, pitch 256
void qkvw_kernel(const float* __restrict__ qw, const float* __restrict__ kw,
                 const float* __restrict__ vw, __nv_bfloat16* __restrict__ dst)
{
    int gid = blockIdx.x * 256 + threadIdx.x;   // Lc*768*128
    int l = gid / (768 * 128);
    int rem = gid - l * 768 * 128;
    int n = rem >> 7;
    int k = (rem & 127) * 2;
    const float* src = (n < 256) ? qw + ((size_t)l * 256 + n) * 256
                     : (n < 512) ? kw + ((size_t)l * 256 + n - 256) * 256
                                 : vw + ((size_t)l * 256 + n - 512) * 256;
    float2 v = *(const float2*)(src + k);
    __nv_bfloat162 hh;
    hh.x = __float2bfloat16(v.x); hh.y = __float2bfloat16(v.y);
    *(__nv_bfloat162*)(dst + ((size_t)l * 768 + n) * 256 + k) = hh;
}

__global__ void bqkv_kernel(const float* __restrict__ qb, const float* __restrict__ kb,
                            const float* __restrict__ vb, float* __restrict__ dst)
{
    int gid = blockIdx.x * 256 + threadIdx.x;   // Lc*768
    int l = gid / 768, n = gid - l * 768;
    float v = (n < 256) ? qb[l * 256 + n]
            : (n < 512) ? kb[l * 256 + n - 256]
                        : vb[l * 256 + n - 512];
    dst[gid] = v;
}

// ---------------------------------------------------------------------------
// HMMA GEMM with 4-stage cp.async pipeline.
// out[8192,N] = A[8192,K3]@W[N,K3]^T + bias, row pitches pA/pW.
//   ep=1: gelu -> [hi|lo] bf16 (obf, pitch 2*Ndim)
//   ep=2: +resid -> fp32 (outp)
//   ep=3: -> bf16 (obf, pitch Ndim)
// Dynamic smem: STG * (A 128x40 + B 128x40) bf16 = 81920 bytes.
// ---------------------------------------------------------------------------
#define SPAD 40
#define STG  4
#define ASTRIDE (128 * SPAD)
#define GEMM_SMEM (2 * STG * ASTRIDE * 2)   // bytes = 81920

__global__ __launch_bounds__(256)
void gemm3_kernel(const __nv_bfloat16* __restrict__ A3, int pA,
                  const __nv_bfloat16* __restrict__ W3, int pW,
                  const float* __restrict__ bias,
                  const float* __restrict__ resid,
                  float* __restrict__ outp,
                  __nv_bfloat16* __restrict__ obf,
                  int Ndim, int K3, int ep)
{
    extern __shared__ __align__(16) __nv_bfloat16 dsm[];
    __nv_bfloat16* sA = dsm;                    // STG stages of 128xSPAD
    __nv_bfloat16* sB = dsm + STG * ASTRIDE;

    const int tid  = threadIdx.x;
    const int wid  = tid >> 5;
    const int lane = tid & 31;
    const int g    = lane >> 2;
    const int t2   = (lane & 3) * 2;
    const int wm   = wid >> 1;
    const int wn   = wid & 1;

    const int row0 = blockIdx.y * 128;
    const int col0 = blockIdx.x * 128;

    const int lr = tid >> 2;
    const int lc = (tid & 3) * 8;
    const __nv_bfloat16* gA0 = A3 + (size_t)(row0 + lr)      * pA + lc;
    const __nv_bfloat16* gA1 = A3 + (size_t)(row0 + lr + 64) * pA + lc;
    const __nv_bfloat16* gB0 = W3 + (size_t)(col0 + lr)      * pW + lc;
    const __nv_bfloat16* gB1 = W3 + (size_t)(col0 + lr + 64) * pW + lc;

    const uint32_t sa0 = smem_u32(sA + lr * SPAD + lc);
    const uint32_t sa1 = smem_u32(sA + (lr + 64) * SPAD + lc);
    const uint32_t sb0 = smem_u32(sB + lr * SPAD + lc);
    const uint32_t sb1 = smem_u32(sB + (lr + 64) * SPAD + lc);

    auto issue_stage = [&](int i) {
        const uint32_t so = (uint32_t)(i & (STG - 1)) * (ASTRIDE * 2);
        const int ko = i * 32;
        asm volatile("cp.async.cg.shared.global [%0], [%1], 16;"
                     :: "r"(sa0 + so), "l"(gA0 + ko) : "memory");
        asm volatile("cp.async.cg.shared.global [%0], [%1], 16;"
                     :: "r"(sa1 + so), "l"(gA1 + ko) : "memory");
        asm volatile("cp.async.cg.shared.global [%0], [%1], 16;"
                     :: "r"(sb0 + so), "l"(gB0 + ko) : "memory");
        asm volatile("cp.async.cg.shared.global [%0], [%1], 16;"
                     :: "r"(sb1 + so), "l"(gB1 + ko) : "memory");
    };

    float acc[2][8][4];
#pragma unroll
    for (int i = 0; i < 2; i++)
#pragma unroll
        for (int j = 0; j < 8; j++)
#pragma unroll
            for (int c = 0; c < 4; c++) acc[i][j][c] = 0.f;

    const int nc = K3 >> 5;

#pragma unroll
    for (int s = 0; s < STG - 1; s++) {
        if (s < nc) issue_stage(s);
        asm volatile("cp.async.commit_group;" ::: "memory");
    }

    for (int i = 0; i < nc; i++) {
        asm volatile("cp.async.wait_group %0;" :: "n"(STG - 2) : "memory");
        __syncthreads();

        const __nv_bfloat16* bufA = sA + (size_t)(i & (STG - 1)) * ASTRIDE;
        const __nv_bfloat16* bufB = sB + (size_t)(i & (STG - 1)) * ASTRIDE;

#pragma unroll
        for (int kk = 0; kk < 32; kk += 16) {
            uint32_t af[2][4];
#pragma unroll
            for (int mi = 0; mi < 2; mi++) {
                const __nv_bfloat16* ap = bufA + (wm * 32 + mi * 16 + g) * SPAD + kk + t2;
                af[mi][0] = *(const uint32_t*)(ap);
                af[mi][1] = *(const uint32_t*)(ap + 8 * SPAD);
                af[mi][2] = *(const uint32_t*)(ap + 8);
                af[mi][3] = *(const uint32_t*)(ap + 8 * SPAD + 8);
            }
#pragma unroll
            for (int ni = 0; ni < 8; ni++) {
                const __nv_bfloat16* bp = bufB + (wn * 64 + ni * 8 + g) * SPAD + kk + t2;
                uint32_t b0 = *(const uint32_t*)(bp);
                uint32_t b1 = *(const uint32_t*)(bp + 8);
#pragma unroll
                for (int mi = 0; mi < 2; mi++) {
                    asm volatile(
                        "mma.sync.aligned.m16n8k16.row.col.f32.bf16.bf16.f32 "
                        "{%0,%1,%2,%3}, {%4,%5,%6,%7}, {%8,%9}, {%0,%1,%2,%3};"
                        : "+f"(acc[mi][ni][0]), "+f"(acc[mi][ni][1]),
                          "+f"(acc[mi][ni][2]), "+f"(acc[mi][ni][3])
                        : "r"(af[mi][0]), "r"(af[mi][1]),
                          "r"(af[mi][2]), "r"(af[mi][3]),
                          "r"(b0), "r"(b1));
                }
            }
        }

        if (i + STG - 1 < nc) issue_stage(i + STG - 1);
        asm volatile("cp.async.commit_group;" ::: "memory");
    }

    // epilogue
#pragma unroll
    for (int mi = 0; mi < 2; mi++) {
        const int r0g = row0 + wm * 32 + mi * 16 + g;
#pragma unroll
        for (int ni = 0; ni < 8; ni++) {
            const int c = col0 + wn * 64 + ni * 8 + t2;
            const float b0 = bias[c], b1 = bias[c + 1];
            float2 v0, v1;
            v0.x = acc[mi][ni][0] + b0;  v0.y = acc[mi][ni][1] + b1;
            v1.x = acc[mi][ni][2] + b0;  v1.y = acc[mi][ni][3] + b1;
            if (ep == 3) {
                *(uint32_t*)(obf + (size_t)r0g * Ndim + c)       = bf2u32(v0.x, v0.y);
                *(uint32_t*)(obf + (size_t)(r0g + 8) * Ndim + c) = bf2u32(v1.x, v1.y);
            } else if (ep == 1) {
                v0.x = gelu_exact(v0.x); v0.y = gelu_exact(v0.y);
                v1.x = gelu_exact(v1.x); v1.y = gelu_exact(v1.y);
                const int P = 2 * Ndim;
                uint32_t h0 = bf2u32(v0.x, v0.y);
                uint32_t h1 = bf2u32(v1.x, v1.y);
                __nv_bfloat162 hb0 = *(__nv_bfloat162*)&h0;
                __nv_bfloat162 hb1 = *(__nv_bfloat162*)&h1;
                uint32_t l0 = bf2u32(v0.x - __bfloat162float(hb0.x),
                                     v0.y - __bfloat162float(hb0.y));
                uint32_t l1 = bf2u32(v1.x - __bfloat162float(hb1.x),
                                     v1.y - __bfloat162float(hb1.y));
                __nv_bfloat16* d0 = obf + (size_t)r0g * P + c;
                __nv_bfloat16* d1 = obf + (size_t)(r0g + 8) * P + c;
                *(uint32_t*)(d0)        = h0;
                *(uint32_t*)(d0 + Ndim) = l0;
                *(uint32_t*)(d1)        = h1;
                *(uint32_t*)(d1 + Ndim) = l1;
            } else {
                float2 r0v = *(const float2*)(resid + (size_t)r0g * Ndim + c);
                float2 r1v = *(const float2*)(resid + (size_t)(r0g + 8) * Ndim + c);
                v0.x += r0v.x; v0.y += r0v.y;
                v1.x += r1v.x; v1.y += r1v.y;
                *(float2*)(outp + (size_t)r0g * Ndim + c)       = v0;
                *(float2*)(outp + (size_t)(r0g + 8) * Ndim + c) = v1;
            }
        }
    }
}

// ---------------------------------------------------------------------------
// Tensor-core flash attention, causal. grid (S/64, B*H), block 128 (4 warps).
// Reads merged QKV (pitch 768: q@0, k@256, v@512); V transposed in-kernel.
// Output: ctx as bf16x3 into a3c (pitch 768).
// ---------------------------------------------------------------------------
__global__ __launch_bounds__(128)
void attn_mma_kernel(const __nv_bfloat16* __restrict__ QKV,
                     __nv_bfloat16* __restrict__ a3c)
{
    __shared__ __align__(16) __nv_bfloat16 Ks[64][40];
    __shared__ __align__(16) __nv_bfloat16 Vs[32][72];

    const int qt  = blockIdx.x;
    const int bh  = blockIdx.y;
    const int b   = bh >> 3;
    const int hh  = bh & 7;
    const int tid = threadIdx.x;
    const int w   = tid >> 5;
    const int lane = tid & 31;
    const int g   = lane >> 2;
    const int t2  = (lane & 3) * 2;

    const int q0 = qt * 64;
    const int r0 = q0 + w * 16 + g;
    const int r1 = r0 + 8;

    uint32_t aq[2][4];
    {
        const __nv_bfloat16* qp  = QKV + ((size_t)(b * Sc + r0)) * 768 + hh * DHc;
        const __nv_bfloat16* qp8 = qp + 8 * 768;
#pragma unroll
        for (int ks = 0; ks < 2; ks++) {
            aq[ks][0] = *(const uint32_t*)(qp  + ks * 16 + t2);
            aq[ks][1] = *(const uint32_t*)(qp8 + ks * 16 + t2);
            aq[ks][2] = *(const uint32_t*)(qp  + ks * 16 + t2 + 8);
            aq[ks][3] = *(const uint32_t*)(qp8 + ks * 16 + t2 + 8);
        }
    }

    float octx[4][4];
#pragma unroll
    for (int i = 0; i < 4; i++)
#pragma unroll
        for (int j = 0; j < 4; j++) octx[i][j] = 0.f;
    float m0 = -1e30f, m1 = -1e30f, l0 = 0.f, l1 = 0.f;
    const float scale = 0.17677669529663689f;

    const int kmax = q0 + 64;
    for (int kt = 0; kt < kmax; kt += 64) {
        __syncthreads();
#pragma unroll
        for (int i = 0; i < 2; i++) {
            int idx = i * 128 + tid;
            int r = idx >> 2, seg = idx & 3;
            *(uint4*)&Ks[r][seg * 8] =
                *(const uint4*)(QKV + ((size_t)(b * Sc + kt + r)) * 768 + 256 + hh * DHc + seg * 8);
        }
        {
            int token = tid >> 1;
            int dh0 = (tid & 1) * 16;
            const __nv_bfloat16* vp =
                QKV + ((size_t)(b * Sc + kt + token)) * 768 + 512 + hh * DHc + dh0;
            uint4 v0 = *(const uint4*)vp;
            uint4 v1 = *(const uint4*)(vp + 8);
            __nv_bfloat16 tmpv[16];
            *(uint4*)&tmpv[0] = v0;
            *(uint4*)&tmpv[8] = v1;
#pragma unroll
            for (int j = 0; j < 16; j++) Vs[dh0 + j][token] = tmpv[j];
        }
        __syncthreads();

        float sacc[8][4];
#pragma unroll
        for (int ni = 0; ni < 8; ni++)
#pragma unroll
            for (int c = 0; c < 4; c++) sacc[ni][c] = 0.f;

#pragma unroll
        for (int ks = 0; ks < 2; ks++) {
#pragma unroll
            for (int ni = 0; ni < 8; ni++) {
                uint32_t b0 = *(const uint32_t*)&Ks[ni * 8 + g][ks * 16 + t2];
                uint32_t b1 = *(const uint32_t*)&Ks[ni * 8 + g][ks * 16 + t2 + 8];
                asm volatile(
                    "mma.sync.aligned.m16n8k16.row.col.f32.bf16.bf16.f32 "
                    "{%0,%1,%2,%3}, {%4,%5,%6,%7}, {%8,%9}, {%0,%1,%2,%3};"
                    : "+f"(sacc[ni][0]), "+f"(sacc[ni][1]),
                      "+f"(sacc[ni][2]), "+f"(sacc[ni][3])
                    : "r"(aq[ks][0]), "r"(aq[ks][1]),
                      "r"(aq[ks][2]), "r"(aq[ks][3]),
                      "r"(b0), "r"(b1));
            }
        }

#pragma unroll
        for (int ni = 0; ni < 8; ni++)
#pragma unroll
            for (int c = 0; c < 4; c++) sacc[ni][c] *= scale;
        if (kt == q0) {
#pragma unroll
            for (int ni = 0; ni < 8; ni++) {
                int c0g = kt + ni * 8 + t2;
                if (c0g     > r0) sacc[ni][0] = -1e30f;
                if (c0g + 1 > r0) sacc[ni][1] = -1e30f;
                if (c0g     > r1) sacc[ni][2] = -1e30f;
                if (c0g + 1 > r1) sacc[ni][3] = -1e30f;
            }
        }

        float tm0 = -1e30f, tm1 = -1e30f;
#pragma unroll
        for (int ni = 0; ni < 8; ni++) {
            tm0 = fmaxf(tm0, fmaxf(sacc[ni][0], sacc[ni][1]));
            tm1 = fmaxf(tm1, fmaxf(sacc[ni][2], sacc[ni][3]));
        }
        tm0 = fmaxf(tm0, __shfl_xor_sync(0xffffffffu, tm0, 1));
        tm0 = fmaxf(tm0, __shfl_xor_sync(0xffffffffu, tm0, 2));
        tm1 = fmaxf(tm1, __shfl_xor_sync(0xffffffffu, tm1, 1));
        tm1 = fmaxf(tm1, __shfl_xor_sync(0xffffffffu, tm1, 2));

        float nm0 = fmaxf(m0, tm0), nm1 = fmaxf(m1, tm1);
        float corr0 = fexp(m0 - nm0), corr1 = fexp(m1 - nm1);
        m0 = nm0; m1 = nm1;
        l0 *= corr0; l1 *= corr1;
#pragma unroll
        for (int nd = 0; nd < 4; nd++) {
            octx[nd][0] *= corr0; octx[nd][1] *= corr0;
            octx[nd][2] *= corr1; octx[nd][3] *= corr1;
        }

        uint32_t pa[4][4];
        float rs0 = 0.f, rs1 = 0.f;
#pragma unroll
        for (int ni = 0; ni < 8; ni++) {
            float p0 = fexp(sacc[ni][0] - m0);
            float p1 = fexp(sacc[ni][1] - m0);
            float p2 = fexp(sacc[ni][2] - m1);
            float p3 = fexp(sacc[ni][3] - m1);
            rs0 += p0 + p1;
            rs1 += p2 + p3;
            const int ks2 = ni >> 1;
            if ((ni & 1) == 0) {
                pa[ks2][0] = bf2u32(p0, p1);
                pa[ks2][1] = bf2u32(p2, p3);
            } else {
                pa[ks2][2] = bf2u32(p0, p1);
                pa[ks2][3] = bf2u32(p2, p3);
            }
        }
        rs0 += __shfl_xor_sync(0xffffffffu, rs0, 1);
        rs0 += __shfl_xor_sync(0xffffffffu, rs0, 2);
        rs1 += __shfl_xor_sync(0xffffffffu, rs1, 1);
        rs1 += __shfl_xor_sync(0xffffffffu, rs1, 2);
        l0 += rs0; l1 += rs1;

#pragma unroll
        for (int ks2 = 0; ks2 < 4; ks2++) {
#pragma unroll
            for (int nd = 0; nd < 4; nd++) {
                uint32_t b0 = *(const uint32_t*)&Vs[nd * 8 + g][ks2 * 16 + t2];
                uint32_t b1 = *(const uint32_t*)&Vs[nd * 8 + g][ks2 * 16 + t2 + 8];
                asm volatile(
                    "mma.sync.aligned.m16n8k16.row.col.f32.bf16.bf16.f32 "
                    "{%0,%1,%2,%3}, {%4,%5,%6,%7}, {%8,%9}, {%0,%1,%2,%3};"
                    : "+f"(octx[nd][0]), "+f"(octx[nd][1]),
                      "+f"(octx[nd][2]), "+f"(octx[nd][3])
                    : "r"(pa[ks2][0]), "r"(pa[ks2][1]),
                      "r"(pa[ks2][2]), "r"(pa[ks2][3]),
                      "r"(b0), "r"(b1));
            }
        }
    }

    const float inv0 = 1.f / l0, inv1 = 1.f / l1;
    const size_t tr0 = (size_t)(b * Sc + r0) * 768;
    const size_t tr1 = (size_t)(b * Sc + r1) * 768;
#pragma unroll
    for (int nd = 0; nd < 4; nd++) {
        const int col = hh * 32 + nd * 8 + t2;
        float x0 = octx[nd][0] * inv0, x1 = octx[nd][1] * inv0;
        float y0 = octx[nd][2] * inv1, y1 = octx[nd][3] * inv1;
        uint32_t h0 = bf2u32(x0, x1);
        uint32_t h1 = bf2u32(y0, y1);
        __nv_bfloat162 hb0 = *(__nv_bfloat162*)&h0;
        __nv_bfloat162 hb1 = *(__nv_bfloat162*)&h1;
        uint32_t lo0 = bf2u32(x0 - __bfloat162float(hb0.x), x1 - __bfloat162float(hb0.y));
        uint32_t lo1 = bf2u32(y0 - __bfloat162float(hb1.x), y1 - __bfloat162float(hb1.y));
        *(uint32_t*)(a3c + tr0 + col)       = h0;
        *(uint32_t*)(a3c + tr0 + 256 + col) = lo0;
        *(uint32_t*)(a3c + tr0 + 512 + col) = h0;
        *(uint32_t*)(a3c + tr1 + col)       = h1;
        *(uint32_t*)(a3c + tr1 + 256 + col) = lo1;
        *(uint32_t*)(a3c + tr1 + 512 + col) = h1;
    }
}

// ---------------------------------------------------------------------------
// Embedding + PE: fp32 h + bf16x3 a3
// ---------------------------------------------------------------------------
__global__ void embed_kernel(const int* __restrict__ x,
                             const float* __restrict__ emb,
                             const float* __restrict__ pe)
{
    int gid = blockIdx.x * 256 + threadIdx.x;
    int t = gid >> 8;
    int d = gid & 255;
    float v = emb[x[t] * Dc + d] + pe[(t & (Sc - 1)) * Dc + d];
    g_h[gid] = v;
    __nv_bfloat16 hi = __float2bfloat16(v);
    __nv_bfloat16 lo = __float2bfloat16(v - __bfloat162float(hi));
    size_t b3 = (size_t)t * 768 + d;
    g_a3[b3]       = hi;
    g_a3[b3 + 256] = lo;
    g_a3[b3 + 512] = hi;
}

// ---------------------------------------------------------------------------
// LayerNorm: warp per row (8 floats/lane), fp32 Y + bf16x3 a3
// ---------------------------------------------------------------------------
__global__ __launch_bounds__(256)
void ln_kernel(const float* __restrict__ X,
               const float* __restrict__ gw,
               const float* __restrict__ bw,
               float* __restrict__ Y,
               __nv_bfloat16* __restrict__ a3)
{
    const int w    = threadIdx.x >> 5;
    const int lane = threadIdx.x & 31;
    const int row  = blockIdx.x * 8 + w;
    const int d    = lane * 8;
    const float* xr = X + (size_t)row * Dc + d;

    float v[8];
    *(float4*)&v[0] = *(const float4*)(xr);
    *(float4*)&v[4] = *(const float4*)(xr + 4);

    float s = v[0] + v[1] + v[2] + v[3] + v[4] + v[5] + v[6] + v[7];
#pragma unroll
    for (int o = 16; o > 0; o >>= 1) s += __shfl_xor_sync(0xffffffffu, s, o);
    const float m = s * (1.0f / Dc);

    float s2 = 0.f;
    float dv[8];
#pragma unroll
    for (int j = 0; j < 8; j++) { dv[j] = v[j] - m; s2 += dv[j] * dv[j]; }
#pragma unroll
    for (int o = 16; o > 0; o >>= 1) s2 += __shfl_xor_sync(0xffffffffu, s2, o);
    const float rstd = rsqrtf(s2 * (1.0f / Dc) + 1e-12f);

    float y[8];
    const float* gwp = gw + d;
    const float* bwp = bw + d;
#pragma unroll
    for (int j = 0; j < 8; j++) y[j] = gwp[j] * dv[j] * rstd + bwp[j];

    float* yr = Y + (size_t)row * Dc + d;
    *(float4*)(yr)     = *(float4*)&y[0];
    *(float4*)(yr + 4) = *(float4*)&y[4];

    __nv_bfloat16 hi[8], lo[8];
#pragma unroll
    for (int j = 0; j < 8; j++) {
        hi[j] = __float2bfloat16(y[j]);
        lo[j] = __float2bfloat16(y[j] - __bfloat162float(hi[j]));
    }
    __nv_bfloat16* a = a3 + (size_t)row * 768 + d;
    *(uint4*)(a)       = *(uint4*)hi;
    *(uint4*)(a + 256) = *(uint4*)lo;
    *(uint4*)(a + 512) = *(uint4*)hi;
}

// ---------------------------------------------------------------------------
// Output projection (M=4)
// ---------------------------------------------------------------------------
__global__ __launch_bounds__(256)
void outproj_kernel(const float* __restrict__ ow,
                    const float* __restrict__ ob,
                    float* __restrict__ out)
{
    const int w    = threadIdx.x >> 5;
    const int lane = threadIdx.x & 31;
    const int t    = blockIdx.x * 8 + w;
    const float* hr = g_h + (size_t)t * Dc;

    float hv[8];
#pragma unroll
    for (int i = 0; i < 8; i++) hv[i] = hr[lane + 32 * i];

#pragma unroll
    for (int m = 0; m < Mc; m++) {
        const float* wr = ow + m * Dc;
        float p = 0.f;
#pragma unroll
        for (int i = 0; i < 8; i++) p += hv[i] * wr[lane + 32 * i];
#pragma unroll
        for (int o = 16; o > 0; o >>= 1) p += __shfl_down_sync(0xffffffffu, p, o);
        if (lane == 0) out[t * Mc + m] = p + ob[m];
    }
}

// ---------------------------------------------------------------------------
// Host orchestration (graph-capturable)
// ---------------------------------------------------------------------------
extern "C" void kernel_launch(void* const* d_in, const int* in_sizes, int n_in,
                              void* d_out, int out_size)
{
    const int*   x     = (const int*)  d_in[0];
    const float* emb   = (const float*)d_in[1];
    const float* pe    = (const float*)d_in[2];
    const float* q_w   = (const float*)d_in[3];
    const float* q_b   = (const float*)d_in[4];
    const float* k_w   = (const float*)d_in[5];
    const float* k_b   = (const float*)d_in[6];
    const float* v_w   = (const float*)d_in[7];
    const float* v_b   = (const float*)d_in[8];
    const float* o_w   = (const float*)d_in[9];
    const float* o_b   = (const float*)d_in[10];
    const float* ln1_g = (const float*)d_in[11];
    const float* ln1_b = (const float*)d_in[12];
    const float* f1_w  = (const float*)d_in[13];
    const float* f1_b  = (const float*)d_in[14];
    const float* f2_w  = (const float*)d_in[15];
    const float* f2_b  = (const float*)d_in[16];
    const float* ln2_g = (const float*)d_in[17];
    const float* ln2_b = (const float*)d_in[18];
    const float* out_w = (const float*)d_in[19];
    const float* out_b = (const float*)d_in[20];
    float* out = (float*)d_out;

    float *h, *tmp, *ao, *bq;
    __nv_bfloat16 *qkv, *a3, *a3c, *a3f, *w3, *wq;
    cudaGetSymbolAddress((void**)&h,   g_h);
    cudaGetSymbolAddress((void**)&tmp, g_tmp);
    cudaGetSymbolAddress((void**)&ao,  g_ao);
    cudaGetSymbolAddress((void**)&qkv, g_qkv);
    cudaGetSymbolAddress((void**)&a3,  g_a3);
    cudaGetSymbolAddress((void**)&a3c, g_a3c);
    cudaGetSymbolAddress((void**)&a3f, g_a3f);
    cudaGetSymbolAddress((void**)&w3,  g_w3);
    cudaGetSymbolAddress((void**)&wq,  g_wq);
    cudaGetSymbolAddress((void**)&bq,  g_bq);

    // allow 80KB dynamic smem for the pipelined GEMM (idempotent)
    cudaFuncSetAttribute(gemm3_kernel,
                         cudaFuncAttributeMaxDynamicSharedMemorySize, GEMM_SMEM);

    // weight conversions
    qkvw_kernel<<<1536, 256>>>(q_w, k_w, v_w, wq);
    bqkv_kernel<<<12, 256>>>(q_b, k_b, v_b, bq);
    convw3_kernel<<<512,  256>>>(o_w,  w3,          Dc, Dc);  // o: 3-term
    convw3_kernel<<<2048, 256>>>(f1_w, w3 + 196608, Dc, Ic);  // f1: 3-term
    convw2_kernel<<<2048, 256>>>(f2_w, w3 + 983040, Ic, Dc);  // f2: 2-term

    embed_kernel<<<TOK * Dc / 256, 256>>>(x, emb, pe);

    const dim3 gQKV(6, 64);             // N=768
    const dim3 gN2(2, 64);              // N=256
    const dim3 gN8(8, 64);              // N=1024
    const dim3 gAttn(Sc / 64, Bc * Hc); // (16, 64)

    for (int l = 0; l < Lc; l++) {
        const __nv_bfloat16* wl = w3 + (size_t)l * LWS;
        const size_t bo = (size_t)l * Dc;

        // merged QKV: 1-term bf16, K=256 (hi slice of a3)
        gemm3_kernel<<<gQKV, 256, GEMM_SMEM>>>(a3, 768, wq + (size_t)l * 196608, 256,
                                               bq + (size_t)l * 768, nullptr, nullptr, qkv,
                                               768, 256, 3);

        attn_mma_kernel<<<gAttn, 128>>>(qkv, a3c);

        // o-proj: 3-term
        gemm3_kernel<<<gN2, 256, GEMM_SMEM>>>(a3c, 768, wl, 768, o_b + bo, h, tmp, nullptr,
                                              Dc, 768, 2);
        ln_kernel<<<TOK / 8, 256>>>(tmp, ln1_g + bo, ln1_b + bo, ao, a3);

        // f1: 3-term in, gelu, 2-term out
        gemm3_kernel<<<gN8, 256, GEMM_SMEM>>>(a3, 768, wl + 196608, 768,
                                              f1_b + (size_t)l * Ic, nullptr, nullptr, a3f,
                                              Ic, 768, 1);
        // f2: 2-term (ff [hi|lo] x W2 [hi|hi])
        gemm3_kernel<<<gN2, 256, GEMM_SMEM>>>(a3f, 2048, wl + 983040, 2048, f2_b + bo,
                                              ao, tmp, nullptr, Dc, 2048, 2);
        ln_kernel<<<TOK / 8, 256>>>(tmp, ln2_g + bo, ln2_b + bo, h, a3);
    }

    outproj_kernel<<<TOK / 8, 256>>>(out_w, out_b, out);
}

// round 17
// speedup vs baseline: 3.6887x; 1.1065x over previous
#include <cuda_runtime.h>
#include <cuda_bf16.h>
#include <math.h>
#include <stdint.h>

#define Lc  4
#define Bc  8
#define Sc  1024
#define Dc  256
#define Hc  8
#define DHc 32
#define Ic  1024
#define Mc  4
#define TOK 8192
#define LWS 1507328ull   // per-layer stride in g_w3 (o:196608 + f1:786432 + f2:524288)

// ---------------------------------------------------------------------------
// Scratch (__device__ globals; no allocations allowed)
// ---------------------------------------------------------------------------
__device__ float g_h  [TOK*Dc];
__device__ float g_tmp[TOK*Dc];
__device__ float g_ao [TOK*Dc];
__device__ __nv_bfloat16 g_qkv[TOK*768];       // [q|k|v] pitch 768
__device__ __nv_bfloat16 g_a3 [TOK*3*Dc];      // [hi|lo|hi] pitch 768
__device__ __nv_bfloat16 g_a3c[TOK*3*Dc];      // ctx bf16x3 pitch 768
__device__ __nv_bfloat16 g_a3f[TOK*2*Ic];      // ff [hi|lo] pitch 2048
__device__ __nv_bfloat16 g_w3 [Lc*LWS];        // o(3t) | f1(3t) | f2(2t)
__device__ __nv_bfloat16 g_wq [Lc*768*256];    // merged qkv weights, 1-term
__device__ float         g_bq [Lc*768];        // merged qkv bias

__device__ __forceinline__ float gelu_exact(float v) {
    return 0.5f * v * (1.0f + erff(v * 0.70710678118654752f));
}

// Fast exp on FMA pipe (no MUFU)
__device__ __forceinline__ float fexp(float x) {
    float y = fmaxf(x * 1.4426950408889634f, -125.0f);
    float t = y + 12582912.0f;
    int   k = __float_as_int(t) - 0x4B400000;
    float f = y - (t - 12582912.0f);
    float p = 9.6181294e-3f;
    p = fmaf(p, f, 5.5504109e-2f);
    p = fmaf(p, f, 2.4022651e-1f);
    p = fmaf(p, f, 6.9314718e-1f);
    p = fmaf(p, f, 1.0f);
    return __int_as_float(__float_as_int(p) + (k << 23));
}

__device__ __forceinline__ uint32_t bf2u32(float a, float b) {
    __nv_bfloat162 t;
    t.x = __float2bfloat16(a);
    t.y = __float2bfloat16(b);
    return *(uint32_t*)&t;
}

__device__ __forceinline__ uint32_t smem_u32(const void* p) {
    uint32_t a;
    asm("{ .reg .u64 t; cvta.to.shared.u64 t, %1; cvt.u32.u64 %0, t; }"
        : "=r"(a) : "l"(p));
    return a;
}

#define LDMX4(r0, r1, r2, r3, addr) \
    asm volatile("ldmatrix.sync.aligned.m8n8.x4.shared.b16 {%0,%1,%2,%3}, [%4];" \
                 : "=r"(r0), "=r"(r1), "=r"(r2), "=r"(r3) : "r"(addr))

// ---------------------------------------------------------------------------
// Weight conversions
// ---------------------------------------------------------------------------
__global__ __launch_bounds__(256)   // 3-term [hi|hi|lo], pitch 3K
void convw3_kernel(const float* __restrict__ src, __nv_bfloat16* __restrict__ dst,
                   int K, int Nper)
{
    int gid = blockIdx.x * 256 + threadIdx.x;
    int kh = K >> 1;
    int l  = gid / (Nper * kh);
    int rem = gid - l * (Nper * kh);
    int n  = rem / kh;
    int k  = (rem - n * kh) * 2;
    float2 v = *(const float2*)(src + ((size_t)l * Nper + n) * K + k);
    __nv_bfloat162 hh, ll;
    hh.x = __float2bfloat16(v.x); hh.y = __float2bfloat16(v.y);
    ll.x = __float2bfloat16(v.x - __bfloat162float(hh.x));
    ll.y = __float2bfloat16(v.y - __bfloat162float(hh.y));
    __nv_bfloat16* d = dst + (size_t)l * LWS + (size_t)n * 3 * K;
    *(__nv_bfloat162*)(d + k)         = hh;
    *(__nv_bfloat162*)(d + K + k)     = hh;
    *(__nv_bfloat162*)(d + 2 * K + k) = ll;
}

__global__ __launch_bounds__(256)   // 2-term [hi|hi], pitch 2K
void convw2_kernel(const float* __restrict__ src, __nv_bfloat16* __restrict__ dst,
                   int K, int Nper)
{
    int gid = blockIdx.x * 256 + threadIdx.x;
    int kh = K >> 1;
    int l  = gid / (Nper * kh);
    int rem = gid - l * (Nper * kh);
    int n  = rem / kh;
    int k  = (rem - n * kh) * 2;
    float2 v = *(const float2*)(src + ((size_t)l * Nper + n) * K + k);
    __nv_bfloat162 hh;
    hh.x = __float2bfloat16(v.x); hh.y = __float2bfloat16(v.y);
    __nv_bfloat16* d = dst + (size_t)l * LWS + (size_t)n * 2 * K;
    *(__nv_bfloat162*)(d + k)     = hh;
    *(__nv_bfloat162*)(d + K + k) = hh;
}

__global__ __launch_bounds__(256)   // merged qkv, 1-term bf16, pitch 256
void qkvw_kernel(const float* __restrict__ qw, const float* __restrict__ kw,
                 const float* __restrict__ vw, __nv_bfloat16* __restrict__ dst)
{
    int gid = blockIdx.x * 256 + threadIdx.x;   // Lc*768*128
    int l = gid / (768 * 128);
    int rem = gid - l * 768 * 128;
    int n = rem >> 7;
    int k = (rem & 127) * 2;
    const float* src = (n < 256) ? qw + ((size_t)l * 256 + n) * 256
                     : (n < 512) ? kw + ((size_t)l * 256 + n - 256) * 256
                                 : vw + ((size_t)l * 256 + n - 512) * 256;
    float2 v = *(const float2*)(src + k);
    __nv_bfloat162 hh;
    hh.x = __float2bfloat16(v.x); hh.y = __float2bfloat16(v.y);
    *(__nv_bfloat162*)(dst + ((size_t)l * 768 + n) * 256 + k) = hh;
}

__global__ void bqkv_kernel(const float* __restrict__ qb, const float* __restrict__ kb,
                            const float* __restrict__ vb, float* __restrict__ dst)
{
    int gid = blockIdx.x * 256 + threadIdx.x;   // Lc*768
    int l = gid / 768, n = gid - l * 768;
    float v = (n < 256) ? qb[l * 256 + n]
            : (n < 512) ? kb[l * 256 + n - 256]
                        : vb[l * 256 + n - 512];
    dst[gid] = v;
}

// ---------------------------------------------------------------------------
// HMMA GEMM with 4-stage cp.async pipeline + ldmatrix fragment loads.
// out[8192,N] = A[8192,K3]@W[N,K3]^T + bias, row pitches pA/pW.
//   ep=1: gelu -> [hi|lo] bf16 (obf, pitch 2*Ndim)
//   ep=2: +resid -> fp32 (outp)
//   ep=3: -> bf16 (obf, pitch Ndim)
// Dynamic smem: STG * (A 128x40 + B 128x40) bf16 = 81920 bytes.
// ---------------------------------------------------------------------------
#define SPAD 40
#define STG  4
#define ASTRIDE (128 * SPAD)
#define GEMM_SMEM (2 * STG * ASTRIDE * 2)   // bytes = 81920

__global__ __launch_bounds__(256)
void gemm3_kernel(const __nv_bfloat16* __restrict__ A3, int pA,
                  const __nv_bfloat16* __restrict__ W3, int pW,
                  const float* __restrict__ bias,
                  const float* __restrict__ resid,
                  float* __restrict__ outp,
                  __nv_bfloat16* __restrict__ obf,
                  int Ndim, int K3, int ep)
{
    extern __shared__ __align__(16) __nv_bfloat16 dsm[];
    __nv_bfloat16* sA = dsm;                    // STG stages of 128xSPAD
    __nv_bfloat16* sB = dsm + STG * ASTRIDE;

    const int tid  = threadIdx.x;
    const int wid  = tid >> 5;
    const int lane = tid & 31;
    const int g    = lane >> 2;
    const int t2   = (lane & 3) * 2;
    const int wm   = wid >> 1;
    const int wn   = wid & 1;

    const int row0 = blockIdx.y * 128;
    const int col0 = blockIdx.x * 128;

    const int lr = tid >> 2;
    const int lc = (tid & 3) * 8;
    const __nv_bfloat16* gA0 = A3 + (size_t)(row0 + lr)      * pA + lc;
    const __nv_bfloat16* gA1 = A3 + (size_t)(row0 + lr + 64) * pA + lc;
    const __nv_bfloat16* gB0 = W3 + (size_t)(col0 + lr)      * pW + lc;
    const __nv_bfloat16* gB1 = W3 + (size_t)(col0 + lr + 64) * pW + lc;

    const uint32_t sa0 = smem_u32(sA + lr * SPAD + lc);
    const uint32_t sa1 = smem_u32(sA + (lr + 64) * SPAD + lc);
    const uint32_t sb0 = smem_u32(sB + lr * SPAD + lc);
    const uint32_t sb1 = smem_u32(sB + (lr + 64) * SPAD + lc);

    // ldmatrix lane->row/col mapping (byte offsets within a stage buffer)
    //  A x4 at (mbase, kk): rows mbase+(lane&15), col kk + (lane>>4)*8
    //  B x4 at (nbase, kk): rows nbase+(lane&7)+((lane>>4)<<3), col kk+((lane>>3)&1)*8
    const uint32_t aOff = (uint32_t)(((wm * 32 + (lane & 15)) * SPAD
                                      + ((lane >> 4) << 3)) * 2);
    const uint32_t bOff = (uint32_t)(((wn * 64 + (lane & 7) + ((lane >> 4) << 3)) * SPAD
                                      + (((lane >> 3) & 1) << 3)) * 2);
    const uint32_t aSmem = smem_u32(sA) + aOff;
    const uint32_t bSmem = smem_u32(sB) + bOff;

    auto issue_stage = [&](int i) {
        const uint32_t so = (uint32_t)(i & (STG - 1)) * (ASTRIDE * 2);
        const int ko = i * 32;
        asm volatile("cp.async.cg.shared.global [%0], [%1], 16;"
                     :: "r"(sa0 + so), "l"(gA0 + ko) : "memory");
        asm volatile("cp.async.cg.shared.global [%0], [%1], 16;"
                     :: "r"(sa1 + so), "l"(gA1 + ko) : "memory");
        asm volatile("cp.async.cg.shared.global [%0], [%1], 16;"
                     :: "r"(sb0 + so), "l"(gB0 + ko) : "memory");
        asm volatile("cp.async.cg.shared.global [%0], [%1], 16;"
                     :: "r"(sb1 + so), "l"(gB1 + ko) : "memory");
    };

    float acc[2][8][4];
#pragma unroll
    for (int i = 0; i < 2; i++)
#pragma unroll
        for (int j = 0; j < 8; j++)
#pragma unroll
            for (int c = 0; c < 4; c++) acc[i][j][c] = 0.f;

    const int nc = K3 >> 5;

#pragma unroll
    for (int s = 0; s < STG - 1; s++) {
        if (s < nc) issue_stage(s);
        asm volatile("cp.async.commit_group;" ::: "memory");
    }

    for (int i = 0; i < nc; i++) {
        asm volatile("cp.async.wait_group %0;" :: "n"(STG - 2) : "memory");
        __syncthreads();

        const uint32_t so = (uint32_t)(i & (STG - 1)) * (ASTRIDE * 2);
        const uint32_t aB = aSmem + so;
        const uint32_t bB = bSmem + so;

#pragma unroll
        for (int kk = 0; kk < 32; kk += 16) {
            uint32_t af[2][4];
#pragma unroll
            for (int mi = 0; mi < 2; mi++)
                LDMX4(af[mi][0], af[mi][1], af[mi][2], af[mi][3],
                      aB + (uint32_t)((mi * 16 * SPAD + kk) * 2));
#pragma unroll
            for (int np = 0; np < 4; np++) {
                uint32_t bq0, bq1, bq2, bq3;
                LDMX4(bq0, bq1, bq2, bq3,
                      bB + (uint32_t)((np * 16 * SPAD + kk) * 2));
#pragma unroll
                for (int mi = 0; mi < 2; mi++) {
                    asm volatile(
                        "mma.sync.aligned.m16n8k16.row.col.f32.bf16.bf16.f32 "
                        "{%0,%1,%2,%3}, {%4,%5,%6,%7}, {%8,%9}, {%0,%1,%2,%3};"
                        : "+f"(acc[mi][np*2][0]), "+f"(acc[mi][np*2][1]),
                          "+f"(acc[mi][np*2][2]), "+f"(acc[mi][np*2][3])
                        : "r"(af[mi][0]), "r"(af[mi][1]),
                          "r"(af[mi][2]), "r"(af[mi][3]),
                          "r"(bq0), "r"(bq1));
                    asm volatile(
                        "mma.sync.aligned.m16n8k16.row.col.f32.bf16.bf16.f32 "
                        "{%0,%1,%2,%3}, {%4,%5,%6,%7}, {%8,%9}, {%0,%1,%2,%3};"
                        : "+f"(acc[mi][np*2+1][0]), "+f"(acc[mi][np*2+1][1]),
                          "+f"(acc[mi][np*2+1][2]), "+f"(acc[mi][np*2+1][3])
                        : "r"(af[mi][0]), "r"(af[mi][1]),
                          "r"(af[mi][2]), "r"(af[mi][3]),
                          "r"(bq2), "r"(bq3));
                }
            }
        }

        if (i + STG - 1 < nc) issue_stage(i + STG - 1);
        asm volatile("cp.async.commit_group;" ::: "memory");
    }

    // epilogue
#pragma unroll
    for (int mi = 0; mi < 2; mi++) {
        const int r0g = row0 + wm * 32 + mi * 16 + g;
#pragma unroll
        for (int ni = 0; ni < 8; ni++) {
            const int c = col0 + wn * 64 + ni * 8 + t2;
            const float b0 = bias[c], b1 = bias[c + 1];
            float2 v0, v1;
            v0.x = acc[mi][ni][0] + b0;  v0.y = acc[mi][ni][1] + b1;
            v1.x = acc[mi][ni][2] + b0;  v1.y = acc[mi][ni][3] + b1;
            if (ep == 3) {
                *(uint32_t*)(obf + (size_t)r0g * Ndim + c)       = bf2u32(v0.x, v0.y);
                *(uint32_t*)(obf + (size_t)(r0g + 8) * Ndim + c) = bf2u32(v1.x, v1.y);
            } else if (ep == 1) {
                v0.x = gelu_exact(v0.x); v0.y = gelu_exact(v0.y);
                v1.x = gelu_exact(v1.x); v1.y = gelu_exact(v1.y);
                const int P = 2 * Ndim;
                uint32_t h0 = bf2u32(v0.x, v0.y);
                uint32_t h1 = bf2u32(v1.x, v1.y);
                __nv_bfloat162 hb0 = *(__nv_bfloat162*)&h0;
                __nv_bfloat162 hb1 = *(__nv_bfloat162*)&h1;
                uint32_t l0 = bf2u32(v0.x - __bfloat162float(hb0.x),
                                     v0.y - __bfloat162float(hb0.y));
                uint32_t l1 = bf2u32(v1.x - __bfloat162float(hb1.x),
                                     v1.y - __bfloat162float(hb1.y));
                __nv_bfloat16* d0 = obf + (size_t)r0g * P + c;
                __nv_bfloat16* d1 = obf + (size_t)(r0g + 8) * P + c;
                *(uint32_t*)(d0)        = h0;
                *(uint32_t*)(d0 + Ndim) = l0;
                *(uint32_t*)(d1)        = h1;
                *(uint32_t*)(d1 + Ndim) = l1;
            } else {
                float2 r0v = *(const float2*)(resid + (size_t)r0g * Ndim + c);
                float2 r1v = *(const float2*)(resid + (size_t)(r0g + 8) * Ndim + c);
                v0.x += r0v.x; v0.y += r0v.y;
                v1.x += r1v.x; v1.y += r1v.y;
                *(float2*)(outp + (size_t)r0g * Ndim + c)       = v0;
                *(float2*)(outp + (size_t)(r0g + 8) * Ndim + c) = v1;
            }
        }
    }
}

// ---------------------------------------------------------------------------
// Tensor-core flash attention, causal. grid (S/64, B*H), block 128 (4 warps).
// Reads merged QKV (pitch 768: q@0, k@256, v@512); V transposed in-kernel.
// Output: ctx as bf16x3 into a3c (pitch 768).
// ---------------------------------------------------------------------------
__global__ __launch_bounds__(128)
void attn_mma_kernel(const __nv_bfloat16* __restrict__ QKV,
                     __nv_bfloat16* __restrict__ a3c)
{
    __shared__ __align__(16) __nv_bfloat16 Ks[64][40];
    __shared__ __align__(16) __nv_bfloat16 Vs[32][72];

    const int qt  = blockIdx.x;
    const int bh  = blockIdx.y;
    const int b   = bh >> 3;
    const int hh  = bh & 7;
    const int tid = threadIdx.x;
    const int w   = tid >> 5;
    const int lane = tid & 31;
    const int g   = lane >> 2;
    const int t2  = (lane & 3) * 2;

    const int q0 = qt * 64;
    const int r0 = q0 + w * 16 + g;
    const int r1 = r0 + 8;

    uint32_t aq[2][4];
    {
        const __nv_bfloat16* qp  = QKV + ((size_t)(b * Sc + r0)) * 768 + hh * DHc;
        const __nv_bfloat16* qp8 = qp + 8 * 768;
#pragma unroll
        for (int ks = 0; ks < 2; ks++) {
            aq[ks][0] = *(const uint32_t*)(qp  + ks * 16 + t2);
            aq[ks][1] = *(const uint32_t*)(qp8 + ks * 16 + t2);
            aq[ks][2] = *(const uint32_t*)(qp  + ks * 16 + t2 + 8);
            aq[ks][3] = *(const uint32_t*)(qp8 + ks * 16 + t2 + 8);
        }
    }

    float octx[4][4];
#pragma unroll
    for (int i = 0; i < 4; i++)
#pragma unroll
        for (int j = 0; j < 4; j++) octx[i][j] = 0.f;
    float m0 = -1e30f, m1 = -1e30f, l0 = 0.f, l1 = 0.f;
    const float scale = 0.17677669529663689f;

    const int kmax = q0 + 64;
    for (int kt = 0; kt < kmax; kt += 64) {
        __syncthreads();
#pragma unroll
        for (int i = 0; i < 2; i++) {
            int idx = i * 128 + tid;
            int r = idx >> 2, seg = idx & 3;
            *(uint4*)&Ks[r][seg * 8] =
                *(const uint4*)(QKV + ((size_t)(b * Sc + kt + r)) * 768 + 256 + hh * DHc + seg * 8);
        }
        {
            int token = tid >> 1;
            int dh0 = (tid & 1) * 16;
            const __nv_bfloat16* vp =
                QKV + ((size_t)(b * Sc + kt + token)) * 768 + 512 + hh * DHc + dh0;
            uint4 v0 = *(const uint4*)vp;
            uint4 v1 = *(const uint4*)(vp + 8);
            __nv_bfloat16 tmpv[16];
            *(uint4*)&tmpv[0] = v0;
            *(uint4*)&tmpv[8] = v1;
#pragma unroll
            for (int j = 0; j < 16; j++) Vs[dh0 + j][token] = tmpv[j];
        }
        __syncthreads();

        float sacc[8][4];
#pragma unroll
        for (int ni = 0; ni < 8; ni++)
#pragma unroll
            for (int c = 0; c < 4; c++) sacc[ni][c] = 0.f;

#pragma unroll
        for (int ks = 0; ks < 2; ks++) {
#pragma unroll
            for (int ni = 0; ni < 8; ni++) {
                uint32_t b0 = *(const uint32_t*)&Ks[ni * 8 + g][ks * 16 + t2];
                uint32_t b1 = *(const uint32_t*)&Ks[ni * 8 + g][ks * 16 + t2 + 8];
                asm volatile(
                    "mma.sync.aligned.m16n8k16.row.col.f32.bf16.bf16.f32 "
                    "{%0,%1,%2,%3}, {%4,%5,%6,%7}, {%8,%9}, {%0,%1,%2,%3};"
                    : "+f"(sacc[ni][0]), "+f"(sacc[ni][1]),
                      "+f"(sacc[ni][2]), "+f"(sacc[ni][3])
                    : "r"(aq[ks][0]), "r"(aq[ks][1]),
                      "r"(aq[ks][2]), "r"(aq[ks][3]),
                      "r"(b0), "r"(b1));
            }
        }

#pragma unroll
        for (int ni = 0; ni < 8; ni++)
#pragma unroll
            for (int c = 0; c < 4; c++) sacc[ni][c] *= scale;
        if (kt == q0) {
#pragma unroll
            for (int ni = 0; ni < 8; ni++) {
                int c0g = kt + ni * 8 + t2;
                if (c0g     > r0) sacc[ni][0] = -1e30f;
                if (c0g + 1 > r0) sacc[ni][1] = -1e30f;
                if (c0g     > r1) sacc[ni][2] = -1e30f;
                if (c0g + 1 > r1) sacc[ni][3] = -1e30f;
            }
        }

        float tm0 = -1e30f, tm1 = -1e30f;
#pragma unroll
        for (int ni = 0; ni < 8; ni++) {
            tm0 = fmaxf(tm0, fmaxf(sacc[ni][0], sacc[ni][1]));
            tm1 = fmaxf(tm1, fmaxf(sacc[ni][2], sacc[ni][3]));
        }
        tm0 = fmaxf(tm0, __shfl_xor_sync(0xffffffffu, tm0, 1));
        tm0 = fmaxf(tm0, __shfl_xor_sync(0xffffffffu, tm0, 2));
        tm1 = fmaxf(tm1, __shfl_xor_sync(0xffffffffu, tm1, 1));
        tm1 = fmaxf(tm1, __shfl_xor_sync(0xffffffffu, tm1, 2));

        float nm0 = fmaxf(m0, tm0), nm1 = fmaxf(m1, tm1);
        float corr0 = fexp(m0 - nm0), corr1 = fexp(m1 - nm1);
        m0 = nm0; m1 = nm1;
        l0 *= corr0; l1 *= corr1;
#pragma unroll
        for (int nd = 0; nd < 4; nd++) {
            octx[nd][0] *= corr0; octx[nd][1] *= corr0;
            octx[nd][2] *= corr1; octx[nd][3] *= corr1;
        }

        uint32_t pa[4][4];
        float rs0 = 0.f, rs1 = 0.f;
#pragma unroll
        for (int ni = 0; ni < 8; ni++) {
            float p0 = fexp(sacc[ni][0] - m0);
            float p1 = fexp(sacc[ni][1] - m0);
            float p2 = fexp(sacc[ni][2] - m1);
            float p3 = fexp(sacc[ni][3] - m1);
            rs0 += p0 + p1;
            rs1 += p2 + p3;
            const int ks2 = ni >> 1;
            if ((ni & 1) == 0) {
                pa[ks2][0] = bf2u32(p0, p1);
                pa[ks2][1] = bf2u32(p2, p3);
            } else {
                pa[ks2][2] = bf2u32(p0, p1);
                pa[ks2][3] = bf2u32(p2, p3);
            }
        }
        rs0 += __shfl_xor_sync(0xffffffffu, rs0, 1);
        rs0 += __shfl_xor_sync(0xffffffffu, rs0, 2);
        rs1 += __shfl_xor_sync(0xffffffffu, rs1, 1);
        rs1 += __shfl_xor_sync(0xffffffffu, rs1, 2);
        l0 += rs0; l1 += rs1;

#pragma unroll
        for (int ks2 = 0; ks2 < 4; ks2++) {
#pragma unroll
            for (int nd = 0; nd < 4; nd++) {
                uint32_t b0 = *(const uint32_t*)&Vs[nd * 8 + g][ks2 * 16 + t2];
                uint32_t b1 = *(const uint32_t*)&Vs[nd * 8 + g][ks2 * 16 + t2 + 8];
                asm volatile(
                    "mma.sync.aligned.m16n8k16.row.col.f32.bf16.bf16.f32 "
                    "{%0,%1,%2,%3}, {%4,%5,%6,%7}, {%8,%9}, {%0,%1,%2,%3};"
                    : "+f"(octx[nd][0]), "+f"(octx[nd][1]),
                      "+f"(octx[nd][2]), "+f"(octx[nd][3])
                    : "r"(pa[ks2][0]), "r"(pa[ks2][1]),
                      "r"(pa[ks2][2]), "r"(pa[ks2][3]),
                      "r"(b0), "r"(b1));
            }
        }
    }

    const float inv0 = 1.f / l0, inv1 = 1.f / l1;
    const size_t tr0 = (size_t)(b * Sc + r0) * 768;
    const size_t tr1 = (size_t)(b * Sc + r1) * 768;
#pragma unroll
    for (int nd = 0; nd < 4; nd++) {
        const int col = hh * 32 + nd * 8 + t2;
        float x0 = octx[nd][0] * inv0, x1 = octx[nd][1] * inv0;
        float y0 = octx[nd][2] * inv1, y1 = octx[nd][3] * inv1;
        uint32_t h0 = bf2u32(x0, x1);
        uint32_t h1 = bf2u32(y0, y1);
        __nv_bfloat162 hb0 = *(__nv_bfloat162*)&h0;
        __nv_bfloat162 hb1 = *(__nv_bfloat162*)&h1;
        uint32_t lo0 = bf2u32(x0 - __bfloat162float(hb0.x), x1 - __bfloat162float(hb0.y));
        uint32_t lo1 = bf2u32(y0 - __bfloat162float(hb1.x), y1 - __bfloat162float(hb1.y));
        *(uint32_t*)(a3c + tr0 + col)       = h0;
        *(uint32_t*)(a3c + tr0 + 256 + col) = lo0;
        *(uint32_t*)(a3c + tr0 + 512 + col) = h0;
        *(uint32_t*)(a3c + tr1 + col)       = h1;
        *(uint32_t*)(a3c + tr1 + 256 + col) = lo1;
        *(uint32_t*)(a3c + tr1 + 512 + col) = h1;
    }
}

// ---------------------------------------------------------------------------
// Embedding + PE: fp32 h + bf16x3 a3
// ---------------------------------------------------------------------------
__global__ void embed_kernel(const int* __restrict__ x,
                             const float* __restrict__ emb,
                             const float* __restrict__ pe)
{
    int gid = blockIdx.x * 256 + threadIdx.x;
    int t = gid >> 8;
    int d = gid & 255;
    float v = emb[x[t] * Dc + d] + pe[(t & (Sc - 1)) * Dc + d];
    g_h[gid] = v;
    __nv_bfloat16 hi = __float2bfloat16(v);
    __nv_bfloat16 lo = __float2bfloat16(v - __bfloat162float(hi));
    size_t b3 = (size_t)t * 768 + d;
    g_a3[b3]       = hi;
    g_a3[b3 + 256] = lo;
    g_a3[b3 + 512] = hi;
}

// ---------------------------------------------------------------------------
// LayerNorm: warp per row (8 floats/lane), fp32 Y + bf16x3 a3
// ---------------------------------------------------------------------------
__global__ __launch_bounds__(256)
void ln_kernel(const float* __restrict__ X,
               const float* __restrict__ gw,
               const float* __restrict__ bw,
               float* __restrict__ Y,
               __nv_bfloat16* __restrict__ a3)
{
    const int w    = threadIdx.x >> 5;
    const int lane = threadIdx.x & 31;
    const int row  = blockIdx.x * 8 + w;
    const int d    = lane * 8;
    const float* xr = X + (size_t)row * Dc + d;

    float v[8];
    *(float4*)&v[0] = *(const float4*)(xr);
    *(float4*)&v[4] = *(const float4*)(xr + 4);

    float s = v[0] + v[1] + v[2] + v[3] + v[4] + v[5] + v[6] + v[7];
#pragma unroll
    for (int o = 16; o > 0; o >>= 1) s += __shfl_xor_sync(0xffffffffu, s, o);
    const float m = s * (1.0f / Dc);

    float s2 = 0.f;
    float dv[8];
#pragma unroll
    for (int j = 0; j < 8; j++) { dv[j] = v[j] - m; s2 += dv[j] * dv[j]; }
#pragma unroll
    for (int o = 16; o > 0; o >>= 1) s2 += __shfl_xor_sync(0xffffffffu, s2, o);
    const float rstd = rsqrtf(s2 * (1.0f / Dc) + 1e-12f);

    float y[8];
    const float* gwp = gw + d;
    const float* bwp = bw + d;
#pragma unroll
    for (int j = 0; j < 8; j++) y[j] = gwp[j] * dv[j] * rstd + bwp[j];

    float* yr = Y + (size_t)row * Dc + d;
    *(float4*)(yr)     = *(float4*)&y[0];
    *(float4*)(yr + 4) = *(float4*)&y[4];

    __nv_bfloat16 hi[8], lo[8];
#pragma unroll
    for (int j = 0; j < 8; j++) {
        hi[j] = __float2bfloat16(y[j]);
        lo[j] = __float2bfloat16(y[j] - __bfloat162float(hi[j]));
    }
    __nv_bfloat16* a = a3 + (size_t)row * 768 + d;
    *(uint4*)(a)       = *(uint4*)hi;
    *(uint4*)(a + 256) = *(uint4*)lo;
    *(uint4*)(a + 512) = *(uint4*)hi;
}

// ---------------------------------------------------------------------------
// Output projection (M=4)
// ---------------------------------------------------------------------------
__global__ __launch_bounds__(256)
void outproj_kernel(const float* __restrict__ ow,
                    const float* __restrict__ ob,
                    float* __restrict__ out)
{
    const int w    = threadIdx.x >> 5;
    const int lane = threadIdx.x & 31;
    const int t    = blockIdx.x * 8 + w;
    const float* hr = g_h + (size_t)t * Dc;

    float hv[8];
#pragma unroll
    for (int i = 0; i < 8; i++) hv[i] = hr[lane + 32 * i];

#pragma unroll
    for (int m = 0; m < Mc; m++) {
        const float* wr = ow + m * Dc;
        float p = 0.f;
#pragma unroll
        for (int i = 0; i < 8; i++) p += hv[i] * wr[lane + 32 * i];
#pragma unroll
        for (int o = 16; o > 0; o >>= 1) p += __shfl_down_sync(0xffffffffu, p, o);
        if (lane == 0) out[t * Mc + m] = p + ob[m];
    }
}

// ---------------------------------------------------------------------------
// Host orchestration (graph-capturable)
// ---------------------------------------------------------------------------
extern "C" void kernel_launch(void* const* d_in, const int* in_sizes, int n_in,
                              void* d_out, int out_size)
{
    const int*   x     = (const int*)  d_in[0];
    const float* emb   = (const float*)d_in[1];
    const float* pe    = (const float*)d_in[2];
    const float* q_w   = (const float*)d_in[3];
    const float* q_b   = (const float*)d_in[4];
    const float* k_w   = (const float*)d_in[5];
    const float* k_b   = (const float*)d_in[6];
    const float* v_w   = (const float*)d_in[7];
    const float* v_b   = (const float*)d_in[8];
    const float* o_w   = (const float*)d_in[9];
    const float* o_b   = (const float*)d_in[10];
    const float* ln1_g = (const float*)d_in[11];
    const float* ln1_b = (const float*)d_in[12];
    const float* f1_w  = (const float*)d_in[13];
    const float* f1_b  = (const float*)d_in[14];
    const float* f2_w  = (const float*)d_in[15];
    const float* f2_b  = (const float*)d_in[16];
    const float* ln2_g = (const float*)d_in[17];
    const float* ln2_b = (const float*)d_in[18];
    const float* out_w = (const float*)d_in[19];
    const float* out_b = (const float*)d_in[20];
    float* out = (float*)d_out;

    float *h, *tmp, *ao, *bq;
    __nv_bfloat16 *qkv, *a3, *a3c, *a3f, *w3, *wq;
    cudaGetSymbolAddress((void**)&h,   g_h);
    cudaGetSymbolAddress((void**)&tmp, g_tmp);
    cudaGetSymbolAddress((void**)&ao,  g_ao);
    cudaGetSymbolAddress((void**)&qkv, g_qkv);
    cudaGetSymbolAddress((void**)&a3,  g_a3);
    cudaGetSymbolAddress((void**)&a3c, g_a3c);
    cudaGetSymbolAddress((void**)&a3f, g_a3f);
    cudaGetSymbolAddress((void**)&w3,  g_w3);
    cudaGetSymbolAddress((void**)&wq,  g_wq);
    cudaGetSymbolAddress((void**)&bq,  g_bq);

    // allow 80KB dynamic smem for the pipelined GEMM (idempotent)
    cudaFuncSetAttribute(gemm3_kernel,
                         cudaFuncAttributeMaxDynamicSharedMemorySize, GEMM_SMEM);

    // weight conversions
    qkvw_kernel<<<1536, 256>>>(q_w, k_w, v_w, wq);
    bqkv_kernel<<<12, 256>>>(q_b, k_b, v_b, bq);
    convw3_kernel<<<512,  256>>>(o_w,  w3,          Dc, Dc);  // o: 3-term
    convw3_kernel<<<2048, 256>>>(f1_w, w3 + 196608, Dc, Ic);  // f1: 3-term
    convw2_kernel<<<2048, 256>>>(f2_w, w3 + 983040, Ic, Dc);  // f2: 2-term

    embed_kernel<<<TOK * Dc / 256, 256>>>(x, emb, pe);

    const dim3 gQKV(6, 64);             // N=768
    const dim3 gN2(2, 64);              // N=256
    const dim3 gN8(8, 64);              // N=1024
    const dim3 gAttn(Sc / 64, Bc * Hc); // (16, 64)

    for (int l = 0; l < Lc; l++) {
        const __nv_bfloat16* wl = w3 + (size_t)l * LWS;
        const size_t bo = (size_t)l * Dc;

        // merged QKV: 1-term bf16, K=256 (hi slice of a3)
        gemm3_kernel<<<gQKV, 256, GEMM_SMEM>>>(a3, 768, wq + (size_t)l * 196608, 256,
                                               bq + (size_t)l * 768, nullptr, nullptr, qkv,
                                               768, 256, 3);

        attn_mma_kernel<<<gAttn, 128>>>(qkv, a3c);

        // o-proj: 3-term
        gemm3_kernel<<<gN2, 256, GEMM_SMEM>>>(a3c, 768, wl, 768, o_b + bo, h, tmp, nullptr,
                                              Dc, 768, 2);
        ln_kernel<<<TOK / 8, 256>>>(tmp, ln1_g + bo, ln1_b + bo, ao, a3);

        // f1: 3-term in, gelu, 2-term out
        gemm3_kernel<<<gN8, 256, GEMM_SMEM>>>(a3, 768, wl + 196608, 768,
                                              f1_b + (size_t)l * Ic, nullptr, nullptr, a3f,
                                              Ic, 768, 1);
        // f2: 2-term (ff [hi|lo] x W2 [hi|hi])
        gemm3_kernel<<<gN2, 256, GEMM_SMEM>>>(a3f, 2048, wl + 983040, 2048, f2_b + bo,
                                              ao, tmp, nullptr, Dc, 2048, 2);
        ln_kernel<<<TOK / 8, 256>>>(tmp, ln2_g + bo, ln2_b + bo, h, a3);
    }

    outproj_kernel<<<TOK / 8, 256>>>(out_w, out_b, out);
}